// round 6
// baseline (speedup 1.0000x reference)
#include <cuda_runtime.h>
#include <cuda_bf16.h>
#include <cstdint>

typedef unsigned int uint;

#define N_NODES 50000
#define N_EDGES 800000
#define N_RELS  65
#define D       64
#define N_GRAPHS 512

#define TILE_M 128
#define MAX_TILES (N_EDGES / TILE_M + N_RELS)   // 6315
#define P_BLOCKS 296
#define RGCN_SMEM 81920   // 2x32KB X bufs + 16KB W

// ---------------- scratch (device globals; no allocation) ----------------
__device__ float d_h0 [N_NODES * D];
__device__ float d_agg[N_NODES * D];
__device__ float d_g [N_GRAPHS * D];
__device__ float d_g2[N_GRAPHS * D];

__device__ uint d_hhi_u[N_NODES * 32];          // bf16 hi plane, 2 per uint
__device__ uint d_hlo_u[N_NODES * 32];          // bf16 lo plane
__device__ uint d_whi_u[3 * N_RELS * 2048];     // W^T hi: [layer][rel][n=c][k=d]
__device__ uint d_wlo_u[3 * N_RELS * 2048];

__device__ int d_counts[N_RELS];                // zero-init; self-resetting
__device__ int d_cursor[N_RELS];
__device__ int d_psrc[N_EDGES];                 // src[perm[i]]
__device__ int d_pdst[N_EDGES];                 // dst[perm[i]]
__device__ int d_tile_rel [MAX_TILES];
__device__ int d_tile_base[MAX_TILES];
__device__ int d_tile_cnt [MAX_TILES];
__device__ int d_num_tiles;

// ---------------- helpers ----------------
__device__ __forceinline__ void red_add_v2(float* p, float a, float b) {
    asm volatile("red.global.add.v2.f32 [%0], {%1, %2};"
                 :: "l"(p), "f"(a), "f"(b) : "memory");
}
__device__ __forceinline__ void red_add_v4(float* p, float a, float b, float c, float d) {
    asm volatile("red.global.add.v4.f32 [%0], {%1, %2, %3, %4};"
                 :: "l"(p), "f"(a), "f"(b), "f"(c), "f"(d) : "memory");
}

__device__ __forceinline__ void mma_bf16(float acc[4], const uint a[4], uint b0, uint b1) {
    asm volatile("mma.sync.aligned.m16n8k16.row.col.f32.bf16.bf16.f32 "
                 "{%0,%1,%2,%3}, {%4,%5,%6,%7}, {%8,%9}, {%0,%1,%2,%3};"
                 : "+f"(acc[0]), "+f"(acc[1]), "+f"(acc[2]), "+f"(acc[3])
                 : "r"(a[0]), "r"(a[1]), "r"(a[2]), "r"(a[3]), "r"(b0), "r"(b1));
}

__device__ __forceinline__ void ldsm_x4(uint r[4], uint32_t addr) {
    asm volatile("ldmatrix.sync.aligned.m8n8.x4.shared.b16 {%0,%1,%2,%3}, [%4];"
                 : "=r"(r[0]), "=r"(r[1]), "=r"(r[2]), "=r"(r[3]) : "r"(addr));
}

__device__ __forceinline__ uint32_t smem_u32(const void* p) {
    uint32_t a;
    asm("{ .reg .u64 t; cvta.to.shared.u64 t, %1; cvt.u32.u64 %0, t; }" : "=r"(a) : "l"(p));
    return a;
}

__device__ __forceinline__ unsigned short bf16_bits(__nv_bfloat16 b) {
    return *reinterpret_cast<unsigned short*>(&b);
}
__device__ __forceinline__ uint packpair(unsigned short a, unsigned short b) {
    return (uint)a | ((uint)b << 16);
}
__device__ __forceinline__ void split2(float v0, float v1, uint& hi, uint& lo) {
    __nv_bfloat16 h0 = __float2bfloat16_rn(v0);
    __nv_bfloat16 h1 = __float2bfloat16_rn(v1);
    float r0 = v0 - __bfloat162float(h0);
    float r1 = v1 - __bfloat162float(h1);
    __nv_bfloat16 l0 = __float2bfloat16_rn(r0);
    __nv_bfloat16 l1 = __float2bfloat16_rn(r1);
    hi = packpair(bf16_bits(h0), bf16_bits(h1));
    lo = packpair(bf16_bits(l0), bf16_bits(l1));
}

// ---------------- prep: conv_x + zero agg/g + conv_w + hist (fused) ---------
__global__ void prep_kernel(const float* __restrict__ nf,
                            const int* __restrict__ et,
                            const float* __restrict__ W1,
                            const float* __restrict__ W2,
                            const float* __restrict__ W3) {
    int idx = blockIdx.x * 256 + threadIdx.x;

    if (idx < N_NODES * 32) {
        float2 v = ((const float2*)nf)[idx];
        uint hi, lo;
        split2(v.x, v.y, hi, lo);
        d_hhi_u[idx] = hi;
        d_hlo_u[idx] = lo;
        ((float2*)d_agg)[idx] = make_float2(0.f, 0.f);
    }
    if (idx < N_GRAPHS * 32) ((float2*)d_g)[idx] = make_float2(0.f, 0.f);

    if (idx < 3 * N_RELS * 64) {
        int l = idx / (N_RELS * 64), rc = idx % (N_RELS * 64);
        int r = rc >> 6, c = rc & 63;
        const float* W = (l == 0 ? W1 : (l == 1 ? W2 : W3)) + (size_t)r * 4096 + c;
        uint4* oh = (uint4*)(d_whi_u + ((size_t)l * N_RELS + r) * 2048);
        uint4* ol = (uint4*)(d_wlo_u + ((size_t)l * N_RELS + r) * 2048);
#pragma unroll
        for (int q = 0; q < 8; q++) {
            uint hu[4], lu[4];
#pragma unroll
            for (int p = 0; p < 4; p++) {
                float v0 = W[(q * 8 + p * 2 + 0) * 64];
                float v1 = W[(q * 8 + p * 2 + 1) * 64];
                split2(v0, v1, hu[p], lu[p]);
            }
            oh[c * 8 + q] = make_uint4(hu[0], hu[1], hu[2], hu[3]);
            ol[c * 8 + q] = make_uint4(lu[0], lu[1], lu[2], lu[3]);
        }
    }

    // histogram (first 256 blocks, grid-stride)
    if (blockIdx.x < 256) {
        __shared__ int sc[N_RELS];
        for (int i = threadIdx.x; i < N_RELS; i += 256) sc[i] = 0;
        __syncthreads();
        for (int e = blockIdx.x * 256 + threadIdx.x; e < N_EDGES; e += 256 * 256)
            atomicAdd(&sc[et[e]], 1);
        __syncthreads();
        for (int i = threadIdx.x; i < N_RELS; i += 256)
            if (sc[i]) atomicAdd(&d_counts[i], sc[i]);
    }
}

// ---------------- scan + tile table (self-resets d_counts) ----------------
__global__ void scan_tiles_kernel() {
    __shared__ int offs[N_RELS];
    __shared__ int tstart[N_RELS];
    __shared__ int tcnt[N_RELS];
    if (threadIdx.x == 0) {
        int off = 0, ts = 0;
        for (int r = 0; r < N_RELS; r++) {
            int c = d_counts[r];
            offs[r] = off; tstart[r] = ts; tcnt[r] = c;
            d_cursor[r] = off;
            off += c;
            ts += (c + TILE_M - 1) / TILE_M;
        }
        d_num_tiles = ts;
    }
    __syncthreads();
    for (int r = threadIdx.x; r < N_RELS; r += blockDim.x) {
        d_counts[r] = 0;                       // ready for next call
        int c = tcnt[r], base = offs[r], t0 = tstart[r];
        int nt = (c + TILE_M - 1) / TILE_M;
        for (int t = 0; t < nt; t++) {
            d_tile_rel [t0 + t] = r;
            d_tile_base[t0 + t] = base + t * TILE_M;
            int rem = c - t * TILE_M;
            d_tile_cnt [t0 + t] = rem < TILE_M ? rem : TILE_M;
        }
    }
}

#define SC_EPT 8
__global__ void scatter_kernel(const int* __restrict__ et,
                               const int* __restrict__ src,
                               const int* __restrict__ dst) {
    __shared__ int lcnt[N_RELS];
    __shared__ int lbase[N_RELS];
    int start = blockIdx.x * blockDim.x * SC_EPT;
    for (int i = threadIdx.x; i < N_RELS; i += blockDim.x) lcnt[i] = 0;
    __syncthreads();
    int myrel[SC_EPT];
#pragma unroll
    for (int q = 0; q < SC_EPT; q++) {
        int e = start + threadIdx.x + q * blockDim.x;
        int r = (e < N_EDGES) ? et[e] : -1;
        myrel[q] = r;
        if (r >= 0) atomicAdd(&lcnt[r], 1);
    }
    __syncthreads();
    for (int i = threadIdx.x; i < N_RELS; i += blockDim.x) {
        int c = lcnt[i];
        lbase[i] = c ? atomicAdd(&d_cursor[i], c) : 0;
        lcnt[i] = 0;
    }
    __syncthreads();
#pragma unroll
    for (int q = 0; q < SC_EPT; q++) {
        int e = start + threadIdx.x + q * blockDim.x;
        int r = myrel[q];
        if (r >= 0) {
            int pos = lbase[r] + atomicAdd(&lcnt[r], 1);
            d_psrc[pos] = src[e];
            d_pdst[pos] = dst[e];
        }
    }
}

// ---------------- RGCN layer: pipelined, direct register scatter ------------
// SMEM: buf0 Xhi [0,16K) Xlo [16K,32K); buf1 [32K,64K); Whi [64K,72K) Wlo [72K,80K)
__global__ void __launch_bounds__(256, 2) rgcn_mma_kernel(int layer)
{
    extern __shared__ __align__(16) uint smem[];
    int nt_total = d_num_tiles;
    int k = (nt_total + P_BLOCKS - 1) / P_BLOCKS;
    int t0 = (int)blockIdx.x * k;
    int t1 = t0 + k; if (t1 > nt_total) t1 = nt_total;
    if (t0 >= t1) return;

    int tid = threadIdx.x;
    int m = tid >> 1, j = tid & 1;
    uint sbase = smem_u32(smem);

    int lane = tid & 31, w = tid >> 5;
    int r0 = w * 16;
    int aRow = r0 + (lane & 7) + (lane & 8);
    int aSel = (lane >> 4) & 1;
    int bRowOff = (lane & 7) + ((lane >> 4) & 1) * 8;
    int bSel = (lane >> 3) & 1;
    int g = lane >> 2, tq = lane & 3;

    int cur_rel = -1;

    auto prefetch = [&](int t, int buf) {
        int base = d_tile_base[t];
        int cnt  = d_tile_cnt[t];
        int ei = base + m;
        int eic = ei < (N_EDGES - 1) ? ei : (N_EDGES - 1);
        int srow = d_psrc[eic];
        uint ssz = (m < cnt) ? 16u : 0u;
        const char* ghi = (const char*)(d_hhi_u + (size_t)srow * 32);
        const char* glo = (const char*)(d_hlo_u + (size_t)srow * 32);
        uint xb = sbase + (uint)buf * 32768u + (uint)m * 128u;
#pragma unroll
        for (int q = 0; q < 4; q++) {
            int lc = j * 4 + q;
            int ph = lc ^ (m & 7);
            asm volatile("cp.async.ca.shared.global [%0], [%1], 16, %2;"
                         :: "r"(xb + (uint)ph * 16u), "l"(ghi + lc * 16), "r"(ssz) : "memory");
            asm volatile("cp.async.ca.shared.global [%0], [%1], 16, %2;"
                         :: "r"(xb + 16384u + (uint)ph * 16u), "l"(glo + lc * 16), "r"(ssz) : "memory");
        }
        asm volatile("cp.async.commit_group;" ::: "memory");
    };

    prefetch(t0, 0);

    for (int t = t0; t < t1; t++) {
        int buf = (t - t0) & 1;

        if (t > t0) __syncthreads();              // prior tile's ldsm/W reads done
        bool has_next = (t + 1 < t1);
        if (has_next) prefetch(t + 1, buf ^ 1);

        int rel = d_tile_rel[t];
        if (rel != cur_rel) {
            cur_rel = rel;
            const uint4* WH = (const uint4*)(d_whi_u + ((size_t)layer * N_RELS + rel) * 2048);
            const uint4* WL = (const uint4*)(d_wlo_u + ((size_t)layer * N_RELS + rel) * 2048);
            uint4* wh4 = (uint4*)((char*)smem + 65536);
            uint4* wl4 = (uint4*)((char*)smem + 65536 + 8192);
#pragma unroll
            for (int i = 0; i < 2; i++) {
                int idx = tid + i * 256;
                int n = idx >> 3, c = idx & 7;
                int ph = c ^ (n & 7);
                wh4[n * 8 + ph] = WH[idx];
                wl4[n * 8 + ph] = WL[idx];
            }
        }

        if (has_next) asm volatile("cp.async.wait_group 1;" ::: "memory");
        else          asm volatile("cp.async.wait_group 0;" ::: "memory");
        __syncthreads();                          // X[t] + W visible

        uint xbB = sbase + (uint)buf * 32768u;
        uint wbB = sbase + 65536u;

        float acc[8][4];
#pragma unroll
        for (int i = 0; i < 8; i++) { acc[i][0] = acc[i][1] = acc[i][2] = acc[i][3] = 0.f; }

#pragma unroll
        for (int ks = 0; ks < 4; ks++) {
            int aChunk = (ks * 2 + aSel) ^ (aRow & 7);
            uint aAddr = xbB + (uint)(aRow * 128 + aChunk * 16);
            uint ah[4], al[4];
            ldsm_x4(ah, aAddr);
            ldsm_x4(al, aAddr + 16384u);
#pragma unroll
            for (int np = 0; np < 4; np++) {
                int n = np * 16 + bRowOff;
                int bChunk = (ks * 2 + bSel) ^ (n & 7);
                uint bAddr = wbB + (uint)(n * 128 + bChunk * 16);
                uint bh[4], bl[4];
                ldsm_x4(bh, bAddr);
                ldsm_x4(bl, bAddr + 8192u);
                mma_bf16(acc[2 * np],     ah, bh[0], bh[1]);
                mma_bf16(acc[2 * np],     ah, bl[0], bl[1]);
                mma_bf16(acc[2 * np],     al, bh[0], bh[1]);
                mma_bf16(acc[2 * np + 1], ah, bh[2], bh[3]);
                mma_bf16(acc[2 * np + 1], ah, bl[2], bl[3]);
                mma_bf16(acc[2 * np + 1], al, bh[2], bh[3]);
            }
        }

        // direct register scatter (no staging, no barrier)
        {
            int baseT = d_tile_base[t], cntT = d_tile_cnt[t];
            int rA = r0 + g, rB = rA + 8;
            int dnA = (rA < cntT) ? d_pdst[baseT + rA] : -1;
            int dnB = (rB < cntT) ? d_pdst[baseT + rB] : -1;
            if (dnA >= 0) {
                float* p = d_agg + (size_t)dnA * 64 + 2 * tq;
#pragma unroll
                for (int nt = 0; nt < 8; nt++)
                    red_add_v2(p + nt * 8, acc[nt][0], acc[nt][1]);
            }
            if (dnB >= 0) {
                float* p = d_agg + (size_t)dnB * 64 + 2 * tq;
#pragma unroll
                for (int nt = 0; nt < 8; nt++)
                    red_add_v2(p + nt * 8, acc[nt][2], acc[nt][3]);
            }
        }
    }
}

// ---------------- bias + relu + bf16 split + agg re-zero ----------------
__global__ void bias_relu_kernel(const float* __restrict__ b, int last) {
    int idx = blockIdx.x * blockDim.x + threadIdx.x;
    if (idx >= N_NODES * 32) return;
    int c0 = (idx * 2) & 63;
    float2 a = ((const float2*)d_agg)[idx];
    ((float2*)d_agg)[idx] = make_float2(0.f, 0.f);
    float v0 = fmaxf(a.x + b[c0],     0.0f);
    float v1 = fmaxf(a.y + b[c0 + 1], 0.0f);
    if (last) ((float2*)d_h0)[idx] = make_float2(v0, v1);
    uint hi, lo;
    split2(v0, v1, hi, lo);
    d_hhi_u[idx] = hi;
    d_hlo_u[idx] = lo;
}

// ---------------- graph sum-pool (reads d_h0) ----------------
__global__ void pool_kernel(const int* __restrict__ gid) {
    int idx = blockIdx.x * blockDim.x + threadIdx.x;
    if (idx >= N_NODES * 16) return;
    int n = idx >> 4, c4 = idx & 15;
    float4 v = ((const float4*)(d_h0 + (size_t)n * 64))[c4];
    float* p = d_g + (size_t)gid[n] * 64 + c4 * 4;
    red_add_v4(p, v.x, v.y, v.z, v.w);
}

// ---------------- FC layers ----------------
__global__ void fc64_kernel(int insel, int outsel,
                            const float* __restrict__ W,
                            const float* __restrict__ b) {
    int idx = blockIdx.x * blockDim.x + threadIdx.x;
    if (idx >= N_GRAPHS * 64) return;
    int r = idx >> 6, c = idx & 63;
    const float* x = (insel == 0 ? d_g : d_g2) + r * 64;
    float acc = b[c];
#pragma unroll
    for (int d = 0; d < 64; d++) acc = fmaf(x[d], W[d * 64 + c], acc);
    float v = fmaxf(acc, 0.0f);
    if (outsel == 0) d_g[idx] = v; else d_g2[idx] = v;
}

__global__ void pred_kernel(const float* __restrict__ W,
                            const float* __restrict__ b,
                            float* __restrict__ out) {
    int idx = blockIdx.x * blockDim.x + threadIdx.x;
    if (idx >= N_GRAPHS * 2) return;
    int r = idx >> 1, c = idx & 1;
    const float* x = d_g2 + r * 64;
    float acc = b[c];
#pragma unroll
    for (int d = 0; d < 64; d++) acc = fmaf(x[d], W[d * 2 + c], acc);
    out[idx] = acc;
}

// ---------------- launch ----------------
extern "C" void kernel_launch(void* const* d_in, const int* in_sizes, int n_in,
                              void* d_out, int out_size) {
    const float* node_feats = (const float*)d_in[0];
    const int*   etypes     = (const int*)d_in[1];
    const int*   src        = (const int*)d_in[2];
    const int*   dst        = (const int*)d_in[3];
    const int*   gid        = (const int*)d_in[4];
    const float* Wr[3] = { (const float*)d_in[5], (const float*)d_in[7], (const float*)d_in[9] };
    const float* br[3] = { (const float*)d_in[6], (const float*)d_in[8], (const float*)d_in[10] };
    const float* fcW[3] = { (const float*)d_in[11], (const float*)d_in[13], (const float*)d_in[15] };
    const float* fcb[3] = { (const float*)d_in[12], (const float*)d_in[14], (const float*)d_in[16] };
    const float* predW = (const float*)d_in[17];
    const float* predb = (const float*)d_in[18];

    static int smem_set = 0;
    if (!smem_set) {
        cudaFuncSetAttribute(rgcn_mma_kernel,
                             cudaFuncAttributeMaxDynamicSharedMemorySize, RGCN_SMEM);
        smem_set = 1;
    }

    const int pgrid = (N_NODES * 32 + 255) / 256;   // 6250

    // 1: prep (conv planes + zero agg/g + hist)
    prep_kernel<<<pgrid, 256>>>(node_feats, etypes, Wr[0], Wr[1], Wr[2]);
    // 2: scan + tile table
    scan_tiles_kernel<<<1, 128>>>();
    // 3: relation-sorted src/dst
    scatter_kernel<<<(N_EDGES + 256 * SC_EPT - 1) / (256 * SC_EPT), 256>>>(etypes, src, dst);

    // 4..9: layers (rgcn is launch #4 -> profiled)
    for (int L = 0; L < 3; L++) {
        rgcn_mma_kernel<<<P_BLOCKS, 256, RGCN_SMEM>>>(L);
        bias_relu_kernel<<<pgrid, 256>>>(br[L], L == 2 ? 1 : 0);
    }

    pool_kernel<<<(N_NODES * 16 + 255) / 256, 256>>>(gid);

    const int fgrid = (N_GRAPHS * 64 + 255) / 256;
    fc64_kernel<<<fgrid, 256>>>(0, 1, fcW[0], fcb[0]);
    fc64_kernel<<<fgrid, 256>>>(1, 0, fcW[1], fcb[1]);
    fc64_kernel<<<fgrid, 256>>>(0, 1, fcW[2], fcb[2]);
    pred_kernel<<<(N_GRAPHS * 2 + 255) / 256, 256>>>(predW, predb, (float*)d_out);
}

// round 7
// speedup vs baseline: 1.2942x; 1.2942x over previous
#include <cuda_runtime.h>
#include <cuda_bf16.h>
#include <cstdint>

typedef unsigned int uint;

#define N_NODES 50000
#define N_EDGES 800000
#define N_RELS  65
#define D       64
#define N_GRAPHS 512

#define TILE_M 128
#define MAX_TILES (N_EDGES / TILE_M + N_RELS)   // 6315
#define P_BLOCKS 296
#define RGCN_SMEM 81920   // 2x32KB X bufs + 16KB W

// ---------------- scratch (device globals; no allocation) ----------------
__device__ float d_h0 [N_NODES * D];
__device__ float d_agg[N_NODES * D];
__device__ float d_g [N_GRAPHS * D];
__device__ float d_g2[N_GRAPHS * D];

__device__ uint d_hhi_u[N_NODES * 32];          // bf16 hi plane, 2 per uint
__device__ uint d_hlo_u[N_NODES * 32];          // bf16 lo plane
__device__ uint d_whi_u[3 * N_RELS * 2048];     // W^T hi: [layer][rel][n=c][k=d]
__device__ uint d_wlo_u[3 * N_RELS * 2048];

__device__ int d_counts[N_RELS];                // zero-init; self-resetting
__device__ int d_cursor[N_RELS];
__device__ int d_psrc[N_EDGES];
__device__ int d_pdst[N_EDGES];
__device__ int d_tile_rel [MAX_TILES];
__device__ int d_tile_base[MAX_TILES];
__device__ int d_tile_cnt [MAX_TILES];
__device__ int d_num_tiles;

// ---------------- helpers ----------------
__device__ __forceinline__ void red_add_v4(float* p, float a, float b, float c, float d) {
    asm volatile("red.global.add.v4.f32 [%0], {%1, %2, %3, %4};"
                 :: "l"(p), "f"(a), "f"(b), "f"(c), "f"(d) : "memory");
}

__device__ __forceinline__ void mma_bf16(float acc[4], const uint a[4], uint b0, uint b1) {
    asm volatile("mma.sync.aligned.m16n8k16.row.col.f32.bf16.bf16.f32 "
                 "{%0,%1,%2,%3}, {%4,%5,%6,%7}, {%8,%9}, {%0,%1,%2,%3};"
                 : "+f"(acc[0]), "+f"(acc[1]), "+f"(acc[2]), "+f"(acc[3])
                 : "r"(a[0]), "r"(a[1]), "r"(a[2]), "r"(a[3]), "r"(b0), "r"(b1));
}

__device__ __forceinline__ void ldsm_x4(uint r[4], uint32_t addr) {
    asm volatile("ldmatrix.sync.aligned.m8n8.x4.shared.b16 {%0,%1,%2,%3}, [%4];"
                 : "=r"(r[0]), "=r"(r[1]), "=r"(r[2]), "=r"(r[3]) : "r"(addr));
}

__device__ __forceinline__ uint32_t smem_u32(const void* p) {
    uint32_t a;
    asm("{ .reg .u64 t; cvta.to.shared.u64 t, %1; cvt.u32.u64 %0, t; }" : "=r"(a) : "l"(p));
    return a;
}

__device__ __forceinline__ unsigned short bf16_bits(__nv_bfloat16 b) {
    return *reinterpret_cast<unsigned short*>(&b);
}
__device__ __forceinline__ uint packpair(unsigned short a, unsigned short b) {
    return (uint)a | ((uint)b << 16);
}
__device__ __forceinline__ void split2(float v0, float v1, uint& hi, uint& lo) {
    __nv_bfloat16 h0 = __float2bfloat16_rn(v0);
    __nv_bfloat16 h1 = __float2bfloat16_rn(v1);
    float r0 = v0 - __bfloat162float(h0);
    float r1 = v1 - __bfloat162float(h1);
    __nv_bfloat16 l0 = __float2bfloat16_rn(r0);
    __nv_bfloat16 l1 = __float2bfloat16_rn(r1);
    hi = packpair(bf16_bits(h0), bf16_bits(h1));
    lo = packpair(bf16_bits(l0), bf16_bits(l1));
}

// ---------------- prep: conv_x + zero agg/g + conv_w + hist (fused) ---------
__global__ void prep_kernel(const float* __restrict__ nf,
                            const int* __restrict__ et,
                            const float* __restrict__ W1,
                            const float* __restrict__ W2,
                            const float* __restrict__ W3) {
    int idx = blockIdx.x * 256 + threadIdx.x;

    if (idx < N_NODES * 32) {
        float2 v = ((const float2*)nf)[idx];
        uint hi, lo;
        split2(v.x, v.y, hi, lo);
        d_hhi_u[idx] = hi;
        d_hlo_u[idx] = lo;
        ((float2*)d_agg)[idx] = make_float2(0.f, 0.f);
    }
    if (idx < N_GRAPHS * 32) ((float2*)d_g)[idx] = make_float2(0.f, 0.f);

    if (idx < 3 * N_RELS * 64) {
        int l = idx / (N_RELS * 64), rc = idx % (N_RELS * 64);
        int r = rc >> 6, c = rc & 63;
        const float* W = (l == 0 ? W1 : (l == 1 ? W2 : W3)) + (size_t)r * 4096 + c;
        uint4* oh = (uint4*)(d_whi_u + ((size_t)l * N_RELS + r) * 2048);
        uint4* ol = (uint4*)(d_wlo_u + ((size_t)l * N_RELS + r) * 2048);
#pragma unroll
        for (int q = 0; q < 8; q++) {
            uint hu[4], lu[4];
#pragma unroll
            for (int p = 0; p < 4; p++) {
                float v0 = W[(q * 8 + p * 2 + 0) * 64];
                float v1 = W[(q * 8 + p * 2 + 1) * 64];
                split2(v0, v1, hu[p], lu[p]);
            }
            oh[c * 8 + q] = make_uint4(hu[0], hu[1], hu[2], hu[3]);
            ol[c * 8 + q] = make_uint4(lu[0], lu[1], lu[2], lu[3]);
        }
    }

    if (blockIdx.x < 256) {
        __shared__ int sc[N_RELS];
        for (int i = threadIdx.x; i < N_RELS; i += 256) sc[i] = 0;
        __syncthreads();
        for (int e = blockIdx.x * 256 + threadIdx.x; e < N_EDGES; e += 256 * 256)
            atomicAdd(&sc[et[e]], 1);
        __syncthreads();
        for (int i = threadIdx.x; i < N_RELS; i += 256)
            if (sc[i]) atomicAdd(&d_counts[i], sc[i]);
    }
}

// ---------------- scan + tile table (self-resets d_counts) ----------------
__global__ void scan_tiles_kernel() {
    __shared__ int offs[N_RELS];
    __shared__ int tstart[N_RELS];
    __shared__ int tcnt[N_RELS];
    if (threadIdx.x == 0) {
        int off = 0, ts = 0;
        for (int r = 0; r < N_RELS; r++) {
            int c = d_counts[r];
            offs[r] = off; tstart[r] = ts; tcnt[r] = c;
            d_cursor[r] = off;
            off += c;
            ts += (c + TILE_M - 1) / TILE_M;
        }
        d_num_tiles = ts;
    }
    __syncthreads();
    for (int r = threadIdx.x; r < N_RELS; r += blockDim.x) {
        d_counts[r] = 0;
        int c = tcnt[r], base = offs[r], t0 = tstart[r];
        int nt = (c + TILE_M - 1) / TILE_M;
        for (int t = 0; t < nt; t++) {
            d_tile_rel [t0 + t] = r;
            d_tile_base[t0 + t] = base + t * TILE_M;
            int rem = c - t * TILE_M;
            d_tile_cnt [t0 + t] = rem < TILE_M ? rem : TILE_M;
        }
    }
}

#define SC_EPT 8
__global__ void scatter_kernel(const int* __restrict__ et,
                               const int* __restrict__ src,
                               const int* __restrict__ dst) {
    __shared__ int lcnt[N_RELS];
    __shared__ int lbase[N_RELS];
    int start = blockIdx.x * blockDim.x * SC_EPT;
    for (int i = threadIdx.x; i < N_RELS; i += blockDim.x) lcnt[i] = 0;
    __syncthreads();
    int myrel[SC_EPT];
#pragma unroll
    for (int q = 0; q < SC_EPT; q++) {
        int e = start + threadIdx.x + q * blockDim.x;
        int r = (e < N_EDGES) ? et[e] : -1;
        myrel[q] = r;
        if (r >= 0) atomicAdd(&lcnt[r], 1);
    }
    __syncthreads();
    for (int i = threadIdx.x; i < N_RELS; i += blockDim.x) {
        int c = lcnt[i];
        lbase[i] = c ? atomicAdd(&d_cursor[i], c) : 0;
        lcnt[i] = 0;
    }
    __syncthreads();
#pragma unroll
    for (int q = 0; q < SC_EPT; q++) {
        int e = start + threadIdx.x + q * blockDim.x;
        int r = myrel[q];
        if (r >= 0) {
            int pos = lbase[r] + atomicAdd(&lcnt[r], 1);
            d_psrc[pos] = src[e];
            d_pdst[pos] = dst[e];
        }
    }
}

// ---------------- RGCN layer: persistent-B, pipelined, staged v4 scatter ----
// Warp grid: 8 warps = 4 edge-blocks(32) x 2 col-halves(32).
// B (W^T) fragments live in registers, reloaded only on relation change.
// SMEM: buf0 Xhi [0,16K) Xlo [16K,32K); buf1 [32K,64K); Whi [64K,72K) Wlo [72K,80K)
__global__ void __launch_bounds__(256, 2) rgcn_mma_kernel(int layer)
{
    extern __shared__ __align__(16) uint smem[];
    int nt_total = d_num_tiles;
    int k = (nt_total + P_BLOCKS - 1) / P_BLOCKS;
    int t0 = (int)blockIdx.x * k;
    int t1 = t0 + k; if (t1 > nt_total) t1 = nt_total;
    if (t0 >= t1) return;

    int tid = threadIdx.x;
    int m = tid >> 1, j = tid & 1;
    uint sbase = smem_u32(smem);
    uint wbB = sbase + 65536u;

    int lane = tid & 31, w = tid >> 5;
    int ebh = w & 3;          // edge block of 32 rows
    int cbh = w >> 2;         // col half of 32
    int aSel = (lane >> 4) & 1;
    int aRowB = ebh * 32 + (lane & 15);
    int bRowOff = (lane & 7) + ((lane >> 4) & 1) * 8;
    int bSel = (lane >> 3) & 1;
    int g = lane >> 2, tq = lane & 3;

    int cur_rel = -1;
    int dn_next = -1;
    uint Bhi[4][2][4], Blo[4][2][4];   // [kstep][n16-half][frag]

    auto prefetch = [&](int t, int buf) {
        int base = d_tile_base[t];
        int cnt  = d_tile_cnt[t];
        int ei = base + m;
        int eic = ei < (N_EDGES - 1) ? ei : (N_EDGES - 1);
        int srow = d_psrc[eic];
        dn_next = (m < cnt) ? d_pdst[eic] : -1;
        uint ssz = (m < cnt) ? 16u : 0u;
        const char* ghi = (const char*)(d_hhi_u + (size_t)srow * 32);
        const char* glo = (const char*)(d_hlo_u + (size_t)srow * 32);
        uint xb = sbase + (uint)buf * 32768u + (uint)m * 128u;
#pragma unroll
        for (int q = 0; q < 4; q++) {
            int lc = j * 4 + q;
            int ph = lc ^ (m & 7);
            asm volatile("cp.async.ca.shared.global [%0], [%1], 16, %2;"
                         :: "r"(xb + (uint)ph * 16u), "l"(ghi + lc * 16), "r"(ssz) : "memory");
            asm volatile("cp.async.ca.shared.global [%0], [%1], 16, %2;"
                         :: "r"(xb + 16384u + (uint)ph * 16u), "l"(glo + lc * 16), "r"(ssz) : "memory");
        }
        asm volatile("cp.async.commit_group;" ::: "memory");
    };

    prefetch(t0, 0);

    for (int t = t0; t < t1; t++) {
        int buf = (t - t0) & 1;
        int dn_cur = dn_next;

        if (t > t0) __syncthreads();              // staging reads of t-1 done
        bool has_next = (t + 1 < t1);
        if (has_next) prefetch(t + 1, buf ^ 1);

        int rel = d_tile_rel[t];
        if (rel != cur_rel) {
            cur_rel = rel;
            const uint4* WH = (const uint4*)(d_whi_u + ((size_t)layer * N_RELS + rel) * 2048);
            const uint4* WL = (const uint4*)(d_wlo_u + ((size_t)layer * N_RELS + rel) * 2048);
            uint4* wh4 = (uint4*)((char*)smem + 65536);
            uint4* wl4 = (uint4*)((char*)smem + 65536 + 8192);
#pragma unroll
            for (int i = 0; i < 2; i++) {
                int idx = tid + i * 256;
                int n = idx >> 3, c = idx & 7;
                int ph = c ^ (n & 7);
                wh4[n * 8 + ph] = WH[idx];
                wl4[n * 8 + ph] = WL[idx];
            }
            __syncthreads();                      // W staged
#pragma unroll
            for (int ks = 0; ks < 4; ks++) {
#pragma unroll
                for (int nh = 0; nh < 2; nh++) {
                    int n = cbh * 32 + nh * 16 + bRowOff;
                    int bChunk = (ks * 2 + bSel) ^ (n & 7);
                    uint bAddr = wbB + (uint)(n * 128 + bChunk * 16);
                    ldsm_x4(Bhi[ks][nh], bAddr);
                    ldsm_x4(Blo[ks][nh], bAddr + 8192u);
                }
            }
        }

        if (has_next) asm volatile("cp.async.wait_group 1;" ::: "memory");
        else          asm volatile("cp.async.wait_group 0;" ::: "memory");
        __syncthreads();                          // X[t] visible

        uint xbB = sbase + (uint)buf * 32768u;

        float acc[2][4][4];
#pragma unroll
        for (int a = 0; a < 2; a++)
#pragma unroll
            for (int b = 0; b < 4; b++) {
                acc[a][b][0] = acc[a][b][1] = acc[a][b][2] = acc[a][b][3] = 0.f;
            }

#pragma unroll
        for (int mb = 0; mb < 2; mb++) {
            int aRow = aRowB + mb * 16;
#pragma unroll
            for (int ks = 0; ks < 4; ks++) {
                int aChunk = (ks * 2 + aSel) ^ (aRow & 7);
                uint aAddr = xbB + (uint)(aRow * 128 + aChunk * 16);
                uint ah[4], al[4];
                ldsm_x4(ah, aAddr);
                ldsm_x4(al, aAddr + 16384u);
#pragma unroll
                for (int nh = 0; nh < 2; nh++) {
                    mma_bf16(acc[mb][2 * nh],     ah, Bhi[ks][nh][0], Bhi[ks][nh][1]);
                    mma_bf16(acc[mb][2 * nh],     ah, Blo[ks][nh][0], Blo[ks][nh][1]);
                    mma_bf16(acc[mb][2 * nh],     al, Bhi[ks][nh][0], Bhi[ks][nh][1]);
                    mma_bf16(acc[mb][2 * nh + 1], ah, Bhi[ks][nh][2], Bhi[ks][nh][3]);
                    mma_bf16(acc[mb][2 * nh + 1], ah, Blo[ks][nh][2], Blo[ks][nh][3]);
                    mma_bf16(acc[mb][2 * nh + 1], al, Bhi[ks][nh][2], Bhi[ks][nh][3]);
                }
            }
        }
        __syncthreads();                          // all A ldsm of buf done

        // stage into the dead X buffer (XOR layout, 64-float rows)
        float* sOutF = (float*)((char*)smem + (size_t)buf * 32768);
#pragma unroll
        for (int mb = 0; mb < 2; mb++) {
#pragma unroll
            for (int n8 = 0; n8 < 4; n8++) {
                int R = ebh * 32 + mb * 16 + g;
                int C = cbh * 32 + n8 * 8 + 2 * tq;
                int pcA = C ^ ((R & 7) << 3);
                *(float2*)&sOutF[R * 64 + pcA] = make_float2(acc[mb][n8][0], acc[mb][n8][1]);
                int R2 = R + 8;
                int pcB = C ^ ((R2 & 7) << 3);
                *(float2*)&sOutF[R2 * 64 + pcB] = make_float2(acc[mb][n8][2], acc[mb][n8][3]);
            }
        }
        __syncthreads();                          // staging visible

        if (dn_cur >= 0) {
            float* p = d_agg + (size_t)dn_cur * 64;
            const float* srw = sOutF + m * 64;
#pragma unroll
            for (int q = 0; q < 8; q++) {
                int c4 = j * 32 + q * 4;
                int pc = c4 ^ ((m & 7) << 3);
                float4 v = *(const float4*)(srw + pc);
                red_add_v4(p + c4, v.x, v.y, v.z, v.w);
            }
        }
    }
}

// ---------------- bias + relu + bf16 split + agg re-zero ----------------
__global__ void bias_relu_kernel(const float* __restrict__ b, int last) {
    int idx = blockIdx.x * blockDim.x + threadIdx.x;
    if (idx >= N_NODES * 32) return;
    int c0 = (idx * 2) & 63;
    float2 a = ((const float2*)d_agg)[idx];
    ((float2*)d_agg)[idx] = make_float2(0.f, 0.f);
    float v0 = fmaxf(a.x + b[c0],     0.0f);
    float v1 = fmaxf(a.y + b[c0 + 1], 0.0f);
    if (last) ((float2*)d_h0)[idx] = make_float2(v0, v1);
    uint hi, lo;
    split2(v0, v1, hi, lo);
    d_hhi_u[idx] = hi;
    d_hlo_u[idx] = lo;
}

// ---------------- graph sum-pool (reads d_h0) ----------------
__global__ void pool_kernel(const int* __restrict__ gid) {
    int idx = blockIdx.x * blockDim.x + threadIdx.x;
    if (idx >= N_NODES * 16) return;
    int n = idx >> 4, c4 = idx & 15;
    float4 v = ((const float4*)(d_h0 + (size_t)n * 64))[c4];
    float* p = d_g + (size_t)gid[n] * 64 + c4 * 4;
    red_add_v4(p, v.x, v.y, v.z, v.w);
}

// ---------------- FC layers ----------------
__global__ void fc64_kernel(int insel, int outsel,
                            const float* __restrict__ W,
                            const float* __restrict__ b) {
    int idx = blockIdx.x * blockDim.x + threadIdx.x;
    if (idx >= N_GRAPHS * 64) return;
    int r = idx >> 6, c = idx & 63;
    const float* x = (insel == 0 ? d_g : d_g2) + r * 64;
    float acc = b[c];
#pragma unroll
    for (int d = 0; d < 64; d++) acc = fmaf(x[d], W[d * 64 + c], acc);
    float v = fmaxf(acc, 0.0f);
    if (outsel == 0) d_g[idx] = v; else d_g2[idx] = v;
}

__global__ void pred_kernel(const float* __restrict__ W,
                            const float* __restrict__ b,
                            float* __restrict__ out) {
    int idx = blockIdx.x * blockDim.x + threadIdx.x;
    if (idx >= N_GRAPHS * 2) return;
    int r = idx >> 1, c = idx & 1;
    const float* x = d_g2 + r * 64;
    float acc = b[c];
#pragma unroll
    for (int d = 0; d < 64; d++) acc = fmaf(x[d], W[d * 2 + c], acc);
    out[idx] = acc;
}

// ---------------- launch ----------------
extern "C" void kernel_launch(void* const* d_in, const int* in_sizes, int n_in,
                              void* d_out, int out_size) {
    const float* node_feats = (const float*)d_in[0];
    const int*   etypes     = (const int*)d_in[1];
    const int*   src        = (const int*)d_in[2];
    const int*   dst        = (const int*)d_in[3];
    const int*   gid        = (const int*)d_in[4];
    const float* Wr[3] = { (const float*)d_in[5], (const float*)d_in[7], (const float*)d_in[9] };
    const float* br[3] = { (const float*)d_in[6], (const float*)d_in[8], (const float*)d_in[10] };
    const float* fcW[3] = { (const float*)d_in[11], (const float*)d_in[13], (const float*)d_in[15] };
    const float* fcb[3] = { (const float*)d_in[12], (const float*)d_in[14], (const float*)d_in[16] };
    const float* predW = (const float*)d_in[17];
    const float* predb = (const float*)d_in[18];

    static int smem_set = 0;
    if (!smem_set) {
        cudaFuncSetAttribute(rgcn_mma_kernel,
                             cudaFuncAttributeMaxDynamicSharedMemorySize, RGCN_SMEM);
        smem_set = 1;
    }

    const int pgrid = (N_NODES * 32 + 255) / 256;

    prep_kernel<<<pgrid, 256>>>(node_feats, etypes, Wr[0], Wr[1], Wr[2]);
    scan_tiles_kernel<<<1, 128>>>();
    scatter_kernel<<<(N_EDGES + 256 * SC_EPT - 1) / (256 * SC_EPT), 256>>>(etypes, src, dst);

    for (int L = 0; L < 3; L++) {
        rgcn_mma_kernel<<<P_BLOCKS, 256, RGCN_SMEM>>>(L);
        bias_relu_kernel<<<pgrid, 256>>>(br[L], L == 2 ? 1 : 0);
    }

    pool_kernel<<<(N_NODES * 16 + 255) / 256, 256>>>(gid);

    const int fgrid = (N_GRAPHS * 64 + 255) / 256;
    fc64_kernel<<<fgrid, 256>>>(0, 1, fcW[0], fcb[0]);
    fc64_kernel<<<fgrid, 256>>>(1, 0, fcW[1], fcb[1]);
    fc64_kernel<<<fgrid, 256>>>(0, 1, fcW[2], fcb[2]);
    pred_kernel<<<(N_GRAPHS * 2 + 255) / 256, 256>>>(predW, predb, (float*)d_out);
}

// round 8
// speedup vs baseline: 1.5481x; 1.1962x over previous
#include <cuda_runtime.h>
#include <cuda_bf16.h>
#include <cstdint>

typedef unsigned int uint;

#define N_NODES 50000
#define N_EDGES 800000
#define N_RELS  65
#define D       64
#define N_GRAPHS 512

#define TILE_M 128
#define MAX_TILES (N_EDGES / TILE_M + N_RELS)   // 6315
#define P_BLOCKS 296
#define RGCN_SMEM 82944   // 2x32KB X bufs + 16KB W + 1KB dst

// ---------------- scratch (device globals; no allocation) ----------------
__device__ float d_h0 [N_NODES * D];
__device__ float d_agg[N_NODES * D];
__device__ float d_g [N_GRAPHS * D];
__device__ float d_g2[N_GRAPHS * D];

__device__ uint d_hhi_u[N_NODES * 32];          // bf16 hi plane, 2 per uint
__device__ uint d_hlo_u[N_NODES * 32];          // bf16 lo plane
__device__ uint d_whi_u[3 * N_RELS * 2048];     // W^T hi: [layer][rel][n=c][k=d]
__device__ uint d_wlo_u[3 * N_RELS * 2048];

__device__ int d_counts[N_RELS];                // zero-init; self-resetting
__device__ int d_cursor[N_RELS];
__device__ int d_psrc[N_EDGES];
__device__ int d_pdst[N_EDGES];
__device__ int d_tile_rel [MAX_TILES];
__device__ int d_tile_base[MAX_TILES];
__device__ int d_tile_cnt [MAX_TILES];
__device__ int d_num_tiles;

// ---------------- helpers ----------------
__device__ __forceinline__ void red_add_v4(float* p, float a, float b, float c, float d) {
    asm volatile("red.global.add.v4.f32 [%0], {%1, %2, %3, %4};"
                 :: "l"(p), "f"(a), "f"(b), "f"(c), "f"(d) : "memory");
}

__device__ __forceinline__ void mma_bf16(float acc[4], const uint a[4], uint b0, uint b1) {
    asm volatile("mma.sync.aligned.m16n8k16.row.col.f32.bf16.bf16.f32 "
                 "{%0,%1,%2,%3}, {%4,%5,%6,%7}, {%8,%9}, {%0,%1,%2,%3};"
                 : "+f"(acc[0]), "+f"(acc[1]), "+f"(acc[2]), "+f"(acc[3])
                 : "r"(a[0]), "r"(a[1]), "r"(a[2]), "r"(a[3]), "r"(b0), "r"(b1));
}

__device__ __forceinline__ void ldsm_x4(uint r[4], uint32_t addr) {
    asm volatile("ldmatrix.sync.aligned.m8n8.x4.shared.b16 {%0,%1,%2,%3}, [%4];"
                 : "=r"(r[0]), "=r"(r[1]), "=r"(r[2]), "=r"(r[3]) : "r"(addr));
}

__device__ __forceinline__ uint32_t smem_u32(const void* p) {
    uint32_t a;
    asm("{ .reg .u64 t; cvta.to.shared.u64 t, %1; cvt.u32.u64 %0, t; }" : "=r"(a) : "l"(p));
    return a;
}

__device__ __forceinline__ unsigned short bf16_bits(__nv_bfloat16 b) {
    return *reinterpret_cast<unsigned short*>(&b);
}
__device__ __forceinline__ uint packpair(unsigned short a, unsigned short b) {
    return (uint)a | ((uint)b << 16);
}
__device__ __forceinline__ void split2(float v0, float v1, uint& hi, uint& lo) {
    __nv_bfloat16 h0 = __float2bfloat16_rn(v0);
    __nv_bfloat16 h1 = __float2bfloat16_rn(v1);
    float r0 = v0 - __bfloat162float(h0);
    float r1 = v1 - __bfloat162float(h1);
    __nv_bfloat16 l0 = __float2bfloat16_rn(r0);
    __nv_bfloat16 l1 = __float2bfloat16_rn(r1);
    hi = packpair(bf16_bits(h0), bf16_bits(h1));
    lo = packpair(bf16_bits(l0), bf16_bits(l1));
}

// ---------------- prep: conv_x + zero agg/g + conv_w + hist (fused) ---------
__global__ void prep_kernel(const float* __restrict__ nf,
                            const int* __restrict__ et,
                            const float* __restrict__ W1,
                            const float* __restrict__ W2,
                            const float* __restrict__ W3) {
    int idx = blockIdx.x * 256 + threadIdx.x;

    if (idx < N_NODES * 32) {
        float2 v = ((const float2*)nf)[idx];
        uint hi, lo;
        split2(v.x, v.y, hi, lo);
        d_hhi_u[idx] = hi;
        d_hlo_u[idx] = lo;
        ((float2*)d_agg)[idx] = make_float2(0.f, 0.f);
    }
    if (idx < N_GRAPHS * 32) ((float2*)d_g)[idx] = make_float2(0.f, 0.f);

    if (idx < 3 * N_RELS * 64) {
        int l = idx / (N_RELS * 64), rc = idx % (N_RELS * 64);
        int r = rc >> 6, c = rc & 63;
        const float* W = (l == 0 ? W1 : (l == 1 ? W2 : W3)) + (size_t)r * 4096 + c;
        uint4* oh = (uint4*)(d_whi_u + ((size_t)l * N_RELS + r) * 2048);
        uint4* ol = (uint4*)(d_wlo_u + ((size_t)l * N_RELS + r) * 2048);
#pragma unroll
        for (int q = 0; q < 8; q++) {
            uint hu[4], lu[4];
#pragma unroll
            for (int p = 0; p < 4; p++) {
                float v0 = W[(q * 8 + p * 2 + 0) * 64];
                float v1 = W[(q * 8 + p * 2 + 1) * 64];
                split2(v0, v1, hu[p], lu[p]);
            }
            oh[c * 8 + q] = make_uint4(hu[0], hu[1], hu[2], hu[3]);
            ol[c * 8 + q] = make_uint4(lu[0], lu[1], lu[2], lu[3]);
        }
    }

    if (blockIdx.x < 256) {
        __shared__ int sc[N_RELS];
        for (int i = threadIdx.x; i < N_RELS; i += 256) sc[i] = 0;
        __syncthreads();
        for (int e = blockIdx.x * 256 + threadIdx.x; e < N_EDGES; e += 256 * 256)
            atomicAdd(&sc[et[e]], 1);
        __syncthreads();
        for (int i = threadIdx.x; i < N_RELS; i += 256)
            if (sc[i]) atomicAdd(&d_counts[i], sc[i]);
    }
}

// ---------------- scan + tile table (self-resets d_counts) ----------------
__global__ void scan_tiles_kernel() {
    __shared__ int offs[N_RELS];
    __shared__ int tstart[N_RELS];
    __shared__ int tcnt[N_RELS];
    if (threadIdx.x == 0) {
        int off = 0, ts = 0;
        for (int r = 0; r < N_RELS; r++) {
            int c = d_counts[r];
            offs[r] = off; tstart[r] = ts; tcnt[r] = c;
            d_cursor[r] = off;
            off += c;
            ts += (c + TILE_M - 1) / TILE_M;
        }
        d_num_tiles = ts;
    }
    __syncthreads();
    for (int r = threadIdx.x; r < N_RELS; r += blockDim.x) {
        d_counts[r] = 0;
        int c = tcnt[r], base = offs[r], t0 = tstart[r];
        int nt = (c + TILE_M - 1) / TILE_M;
        for (int t = 0; t < nt; t++) {
            d_tile_rel [t0 + t] = r;
            d_tile_base[t0 + t] = base + t * TILE_M;
            int rem = c - t * TILE_M;
            d_tile_cnt [t0 + t] = rem < TILE_M ? rem : TILE_M;
        }
    }
}

#define SC_EPT 8
__global__ void scatter_kernel(const int* __restrict__ et,
                               const int* __restrict__ src,
                               const int* __restrict__ dst) {
    __shared__ int lcnt[N_RELS];
    __shared__ int lbase[N_RELS];
    int start = blockIdx.x * blockDim.x * SC_EPT;
    for (int i = threadIdx.x; i < N_RELS; i += blockDim.x) lcnt[i] = 0;
    __syncthreads();
    int myrel[SC_EPT];
#pragma unroll
    for (int q = 0; q < SC_EPT; q++) {
        int e = start + threadIdx.x + q * blockDim.x;
        int r = (e < N_EDGES) ? et[e] : -1;
        myrel[q] = r;
        if (r >= 0) atomicAdd(&lcnt[r], 1);
    }
    __syncthreads();
    for (int i = threadIdx.x; i < N_RELS; i += blockDim.x) {
        int c = lcnt[i];
        lbase[i] = c ? atomicAdd(&d_cursor[i], c) : 0;
        lcnt[i] = 0;
    }
    __syncthreads();
#pragma unroll
    for (int q = 0; q < SC_EPT; q++) {
        int e = start + threadIdx.x + q * blockDim.x;
        int r = myrel[q];
        if (r >= 0) {
            int pos = lbase[r] + atomicAdd(&lcnt[r], 1);
            d_psrc[pos] = src[e];
            d_pdst[pos] = dst[e];
        }
    }
}

// ---------------- RGCN layer: persistent-B + coalesced gather/scatter -------
// SMEM: buf0 Xhi [0,16K) Xlo [16K,32K); buf1 [32K,64K);
//       Whi [64K,72K) Wlo [72K,80K); dst[2][128] at [80K, 81K)
__global__ void __launch_bounds__(256, 2) rgcn_mma_kernel(int layer)
{
    extern __shared__ __align__(16) uint smem[];
    int nt_total = d_num_tiles;
    int k = (nt_total + P_BLOCKS - 1) / P_BLOCKS;
    int t0 = (int)blockIdx.x * k;
    int t1 = t0 + k; if (t1 > nt_total) t1 = nt_total;
    if (t0 >= t1) return;

    int tid = threadIdx.x;
    uint sbase = smem_u32(smem);
    uint wbB = sbase + 65536u;
    int* s_dstS = (int*)((char*)smem + 81920);   // [2][128]

    int lane = tid & 31, w = tid >> 5;
    int ebh = w & 3;          // edge block of 32 rows
    int cbh = w >> 2;         // col half of 32
    int aSel = (lane >> 4) & 1;
    int aRowB = ebh * 32 + (lane & 15);
    int bRowOff = (lane & 7) + ((lane >> 4) & 1) * 8;
    int bSel = (lane >> 3) & 1;
    int g = lane >> 2, tq = lane & 3;

    // coalesced gather map: 8 threads per edge row
    int gm0 = tid >> 3, gc8 = tid & 7;
    // coalesced scatter map: 16 threads per edge row
    int sm0 = tid >> 4, sc16 = tid & 15;

    int cur_rel = -1;
    uint Bhi[4][2][4], Blo[4][2][4];   // [kstep][n16-half][frag]

    auto prefetch = [&](int t, int buf) {
        int base = d_tile_base[t];
        int cnt  = d_tile_cnt[t];
        uint xb = sbase + (uint)buf * 32768u;
        int* sd = s_dstS + buf * 128;
#pragma unroll
        for (int p = 0; p < 4; p++) {
            int m = gm0 + p * 32;
            int ei = base + m;
            int eic = ei < (N_EDGES - 1) ? ei : (N_EDGES - 1);
            int srow = d_psrc[eic];
            uint ssz = (m < cnt) ? 16u : 0u;
            const char* ghi = (const char*)(d_hhi_u + (size_t)srow * 32) + gc8 * 16;
            const char* glo = (const char*)(d_hlo_u + (size_t)srow * 32) + gc8 * 16;
            int ph = gc8 ^ (m & 7);
            uint dsthi = xb + (uint)(m * 128 + ph * 16);
            asm volatile("cp.async.ca.shared.global [%0], [%1], 16, %2;"
                         :: "r"(dsthi), "l"(ghi), "r"(ssz) : "memory");
            asm volatile("cp.async.ca.shared.global [%0], [%1], 16, %2;"
                         :: "r"(dsthi + 16384u), "l"(glo), "r"(ssz) : "memory");
            if (gc8 == 0) sd[m] = (m < cnt) ? d_pdst[eic] : -1;
        }
        asm volatile("cp.async.commit_group;" ::: "memory");
    };

    prefetch(t0, 0);

    for (int t = t0; t < t1; t++) {
        int buf = (t - t0) & 1;

        if (t > t0) __syncthreads();              // scatter reads of t-1 done
        bool has_next = (t + 1 < t1);
        if (has_next) prefetch(t + 1, buf ^ 1);

        int rel = d_tile_rel[t];
        if (rel != cur_rel) {
            cur_rel = rel;
            const uint4* WH = (const uint4*)(d_whi_u + ((size_t)layer * N_RELS + rel) * 2048);
            const uint4* WL = (const uint4*)(d_wlo_u + ((size_t)layer * N_RELS + rel) * 2048);
            uint4* wh4 = (uint4*)((char*)smem + 65536);
            uint4* wl4 = (uint4*)((char*)smem + 65536 + 8192);
#pragma unroll
            for (int i = 0; i < 2; i++) {
                int idx = tid + i * 256;
                int n = idx >> 3, c = idx & 7;
                int ph = c ^ (n & 7);
                wh4[n * 8 + ph] = WH[idx];
                wl4[n * 8 + ph] = WL[idx];
            }
            __syncthreads();                      // W staged
#pragma unroll
            for (int ks = 0; ks < 4; ks++) {
#pragma unroll
                for (int nh = 0; nh < 2; nh++) {
                    int n = cbh * 32 + nh * 16 + bRowOff;
                    int bChunk = (ks * 2 + bSel) ^ (n & 7);
                    uint bAddr = wbB + (uint)(n * 128 + bChunk * 16);
                    ldsm_x4(Bhi[ks][nh], bAddr);
                    ldsm_x4(Blo[ks][nh], bAddr + 8192u);
                }
            }
        }

        if (has_next) asm volatile("cp.async.wait_group 1;" ::: "memory");
        else          asm volatile("cp.async.wait_group 0;" ::: "memory");
        __syncthreads();                          // X[t] + s_dst visible

        uint xbB = sbase + (uint)buf * 32768u;

        float acc[2][4][4];
#pragma unroll
        for (int a = 0; a < 2; a++)
#pragma unroll
            for (int b = 0; b < 4; b++) {
                acc[a][b][0] = acc[a][b][1] = acc[a][b][2] = acc[a][b][3] = 0.f;
            }

#pragma unroll
        for (int mb = 0; mb < 2; mb++) {
            int aRow = aRowB + mb * 16;
#pragma unroll
            for (int ks = 0; ks < 4; ks++) {
                int aChunk = (ks * 2 + aSel) ^ (aRow & 7);
                uint aAddr = xbB + (uint)(aRow * 128 + aChunk * 16);
                uint ah[4], al[4];
                ldsm_x4(ah, aAddr);
                ldsm_x4(al, aAddr + 16384u);
#pragma unroll
                for (int nh = 0; nh < 2; nh++) {
                    mma_bf16(acc[mb][2 * nh],     ah, Bhi[ks][nh][0], Bhi[ks][nh][1]);
                    mma_bf16(acc[mb][2 * nh],     ah, Blo[ks][nh][0], Blo[ks][nh][1]);
                    mma_bf16(acc[mb][2 * nh],     al, Bhi[ks][nh][0], Bhi[ks][nh][1]);
                    mma_bf16(acc[mb][2 * nh + 1], ah, Bhi[ks][nh][2], Bhi[ks][nh][3]);
                    mma_bf16(acc[mb][2 * nh + 1], ah, Blo[ks][nh][2], Blo[ks][nh][3]);
                    mma_bf16(acc[mb][2 * nh + 1], al, Bhi[ks][nh][2], Bhi[ks][nh][3]);
                }
            }
        }
        __syncthreads();                          // all A ldsm of buf done

        // stage into the dead X buffer (XOR layout, 64-float rows)
        float* sOutF = (float*)((char*)smem + (size_t)buf * 32768);
#pragma unroll
        for (int mb = 0; mb < 2; mb++) {
#pragma unroll
            for (int n8 = 0; n8 < 4; n8++) {
                int R = ebh * 32 + mb * 16 + g;
                int C = cbh * 32 + n8 * 8 + 2 * tq;
                int pcA = C ^ ((R & 7) << 3);
                *(float2*)&sOutF[R * 64 + pcA] = make_float2(acc[mb][n8][0], acc[mb][n8][1]);
                int R2 = R + 8;
                int pcB = C ^ ((R2 & 7) << 3);
                *(float2*)&sOutF[R2 * 64 + pcB] = make_float2(acc[mb][n8][2], acc[mb][n8][3]);
            }
        }
        __syncthreads();                          // staging visible

        // coalesced scatter: 16 threads per edge -> whole 256B row per half-warp
        {
            int* sd = s_dstS + buf * 128;
#pragma unroll
            for (int p = 0; p < 8; p++) {
                int m = sm0 + p * 16;
                int dn = sd[m];
                if (dn >= 0) {
                    int pc = (sc16 * 4) ^ ((m & 7) << 3);
                    float4 v = *(const float4*)&sOutF[m * 64 + pc];
                    red_add_v4(d_agg + (size_t)dn * 64 + sc16 * 4, v.x, v.y, v.z, v.w);
                }
            }
        }
    }
}

// ---------------- bias + relu + bf16 split + agg re-zero ----------------
__global__ void bias_relu_kernel(const float* __restrict__ b, int last) {
    int idx = blockIdx.x * blockDim.x + threadIdx.x;
    if (idx >= N_NODES * 32) return;
    int c0 = (idx * 2) & 63;
    float2 a = ((const float2*)d_agg)[idx];
    ((float2*)d_agg)[idx] = make_float2(0.f, 0.f);
    float v0 = fmaxf(a.x + b[c0],     0.0f);
    float v1 = fmaxf(a.y + b[c0 + 1], 0.0f);
    if (last) ((float2*)d_h0)[idx] = make_float2(v0, v1);
    uint hi, lo;
    split2(v0, v1, hi, lo);
    d_hhi_u[idx] = hi;
    d_hlo_u[idx] = lo;
}

// ---------------- graph sum-pool (reads d_h0) ----------------
__global__ void pool_kernel(const int* __restrict__ gid) {
    int idx = blockIdx.x * blockDim.x + threadIdx.x;
    if (idx >= N_NODES * 16) return;
    int n = idx >> 4, c4 = idx & 15;
    float4 v = ((const float4*)(d_h0 + (size_t)n * 64))[c4];
    float* p = d_g + (size_t)gid[n] * 64 + c4 * 4;
    red_add_v4(p, v.x, v.y, v.z, v.w);
}

// ---------------- FC layers ----------------
__global__ void fc64_kernel(int insel, int outsel,
                            const float* __restrict__ W,
                            const float* __restrict__ b) {
    int idx = blockIdx.x * blockDim.x + threadIdx.x;
    if (idx >= N_GRAPHS * 64) return;
    int r = idx >> 6, c = idx & 63;
    const float* x = (insel == 0 ? d_g : d_g2) + r * 64;
    float acc = b[c];
#pragma unroll
    for (int d = 0; d < 64; d++) acc = fmaf(x[d], W[d * 64 + c], acc);
    float v = fmaxf(acc, 0.0f);
    if (outsel == 0) d_g[idx] = v; else d_g2[idx] = v;
}

__global__ void pred_kernel(const float* __restrict__ W,
                            const float* __restrict__ b,
                            float* __restrict__ out) {
    int idx = blockIdx.x * blockDim.x + threadIdx.x;
    if (idx >= N_GRAPHS * 2) return;
    int r = idx >> 1, c = idx & 1;
    const float* x = d_g2 + r * 64;
    float acc = b[c];
#pragma unroll
    for (int d = 0; d < 64; d++) acc = fmaf(x[d], W[d * 2 + c], acc);
    out[idx] = acc;
}

// ---------------- launch ----------------
extern "C" void kernel_launch(void* const* d_in, const int* in_sizes, int n_in,
                              void* d_out, int out_size) {
    const float* node_feats = (const float*)d_in[0];
    const int*   etypes     = (const int*)d_in[1];
    const int*   src        = (const int*)d_in[2];
    const int*   dst        = (const int*)d_in[3];
    const int*   gid        = (const int*)d_in[4];
    const float* Wr[3] = { (const float*)d_in[5], (const float*)d_in[7], (const float*)d_in[9] };
    const float* br[3] = { (const float*)d_in[6], (const float*)d_in[8], (const float*)d_in[10] };
    const float* fcW[3] = { (const float*)d_in[11], (const float*)d_in[13], (const float*)d_in[15] };
    const float* fcb[3] = { (const float*)d_in[12], (const float*)d_in[14], (const float*)d_in[16] };
    const float* predW = (const float*)d_in[17];
    const float* predb = (const float*)d_in[18];

    static int smem_set = 0;
    if (!smem_set) {
        cudaFuncSetAttribute(rgcn_mma_kernel,
                             cudaFuncAttributeMaxDynamicSharedMemorySize, RGCN_SMEM);
        smem_set = 1;
    }

    const int pgrid = (N_NODES * 32 + 255) / 256;

    prep_kernel<<<pgrid, 256>>>(node_feats, etypes, Wr[0], Wr[1], Wr[2]);
    scan_tiles_kernel<<<1, 128>>>();
    scatter_kernel<<<(N_EDGES + 256 * SC_EPT - 1) / (256 * SC_EPT), 256>>>(etypes, src, dst);

    for (int L = 0; L < 3; L++) {
        rgcn_mma_kernel<<<P_BLOCKS, 256, RGCN_SMEM>>>(L);
        bias_relu_kernel<<<pgrid, 256>>>(br[L], L == 2 ? 1 : 0);
    }

    pool_kernel<<<(N_NODES * 16 + 255) / 256, 256>>>(gid);

    const int fgrid = (N_GRAPHS * 64 + 255) / 256;
    fc64_kernel<<<fgrid, 256>>>(0, 1, fcW[0], fcb[0]);
    fc64_kernel<<<fgrid, 256>>>(1, 0, fcW[1], fcb[1]);
    fc64_kernel<<<fgrid, 256>>>(0, 1, fcW[2], fcb[2]);
    pred_kernel<<<(N_GRAPHS * 2 + 255) / 256, 256>>>(predW, predb, (float*)d_out);
}

// round 9
// speedup vs baseline: 1.6600x; 1.0722x over previous
#include <cuda_runtime.h>
#include <cuda_bf16.h>
#include <cstdint>

typedef unsigned int uint;

#define N_NODES 50000
#define N_EDGES 800000
#define N_RELS  65
#define D       64
#define N_GRAPHS 512

#define TILE_M 128
#define MAX_TILES (N_EDGES / TILE_M + N_RELS)   // 6315
#define P_BLOCKS 296
#define RGCN_SMEM 82944   // 2x32KB X bufs + 16KB W + 1KB dst

// ---------------- scratch (device globals; no allocation) ----------------
__device__ float d_h0 [N_NODES * D];
__device__ float d_agg[N_NODES * D];
__device__ float d_g [N_GRAPHS * D];
__device__ float d_g2[N_GRAPHS * D];

__device__ uint d_hhi_u[N_NODES * 32];          // bf16 hi plane, 2 per uint
__device__ uint d_hlo_u[N_NODES * 32];          // bf16 lo plane
__device__ uint d_whi_u[3 * N_RELS * 2048];     // W^T hi: [layer][rel][n=c][k=d]
__device__ uint d_wlo_u[3 * N_RELS * 2048];

__device__ int d_counts[N_RELS];                // zero-init; self-resetting
__device__ int d_cursor[N_RELS];
__device__ int d_psrc[N_EDGES];
__device__ int d_pdst[N_EDGES];
__device__ int d_tile_rel [MAX_TILES];
__device__ int d_tile_base[MAX_TILES];
__device__ int d_tile_cnt [MAX_TILES];
__device__ int d_num_tiles;

// ---------------- helpers ----------------
__device__ __forceinline__ void red_add_v4(float* p, float a, float b, float c, float d) {
    asm volatile("red.global.add.v4.f32 [%0], {%1, %2, %3, %4};"
                 :: "l"(p), "f"(a), "f"(b), "f"(c), "f"(d) : "memory");
}

__device__ __forceinline__ void mma_bf16(float acc[4], const uint a[4], uint b0, uint b1) {
    asm volatile("mma.sync.aligned.m16n8k16.row.col.f32.bf16.bf16.f32 "
                 "{%0,%1,%2,%3}, {%4,%5,%6,%7}, {%8,%9}, {%0,%1,%2,%3};"
                 : "+f"(acc[0]), "+f"(acc[1]), "+f"(acc[2]), "+f"(acc[3])
                 : "r"(a[0]), "r"(a[1]), "r"(a[2]), "r"(a[3]), "r"(b0), "r"(b1));
}

__device__ __forceinline__ void ldsm_x4(uint r[4], uint32_t addr) {
    asm volatile("ldmatrix.sync.aligned.m8n8.x4.shared.b16 {%0,%1,%2,%3}, [%4];"
                 : "=r"(r[0]), "=r"(r[1]), "=r"(r[2]), "=r"(r[3]) : "r"(addr));
}

__device__ __forceinline__ uint32_t smem_u32(const void* p) {
    uint32_t a;
    asm("{ .reg .u64 t; cvta.to.shared.u64 t, %1; cvt.u32.u64 %0, t; }" : "=r"(a) : "l"(p));
    return a;
}

__device__ __forceinline__ unsigned short bf16_bits(__nv_bfloat16 b) {
    return *reinterpret_cast<unsigned short*>(&b);
}
__device__ __forceinline__ uint packpair(unsigned short a, unsigned short b) {
    return (uint)a | ((uint)b << 16);
}
__device__ __forceinline__ void split2(float v0, float v1, uint& hi, uint& lo) {
    __nv_bfloat16 h0 = __float2bfloat16_rn(v0);
    __nv_bfloat16 h1 = __float2bfloat16_rn(v1);
    float r0 = v0 - __bfloat162float(h0);
    float r1 = v1 - __bfloat162float(h1);
    __nv_bfloat16 l0 = __float2bfloat16_rn(r0);
    __nv_bfloat16 l1 = __float2bfloat16_rn(r1);
    hi = packpair(bf16_bits(h0), bf16_bits(h1));
    lo = packpair(bf16_bits(l0), bf16_bits(l1));
}

// ---------------- prep: conv_x + zero agg/g + conv_w + hist (fused) ---------
__global__ void prep_kernel(const float* __restrict__ nf,
                            const int* __restrict__ et,
                            const float* __restrict__ W1,
                            const float* __restrict__ W2,
                            const float* __restrict__ W3) {
    int idx = blockIdx.x * 256 + threadIdx.x;

    if (idx < N_NODES * 32) {
        float2 v = ((const float2*)nf)[idx];
        uint hi, lo;
        split2(v.x, v.y, hi, lo);
        d_hhi_u[idx] = hi;
        d_hlo_u[idx] = lo;
        ((float2*)d_agg)[idx] = make_float2(0.f, 0.f);
    }
    if (idx < N_GRAPHS * 32) ((float2*)d_g)[idx] = make_float2(0.f, 0.f);

    if (idx < 3 * N_RELS * 64) {
        int l = idx / (N_RELS * 64), rc = idx % (N_RELS * 64);
        int r = rc >> 6, c = rc & 63;
        const float* W = (l == 0 ? W1 : (l == 1 ? W2 : W3)) + (size_t)r * 4096 + c;
        uint4* oh = (uint4*)(d_whi_u + ((size_t)l * N_RELS + r) * 2048);
        uint4* ol = (uint4*)(d_wlo_u + ((size_t)l * N_RELS + r) * 2048);
#pragma unroll
        for (int q = 0; q < 8; q++) {
            uint hu[4], lu[4];
#pragma unroll
            for (int p = 0; p < 4; p++) {
                float v0 = W[(q * 8 + p * 2 + 0) * 64];
                float v1 = W[(q * 8 + p * 2 + 1) * 64];
                split2(v0, v1, hu[p], lu[p]);
            }
            oh[c * 8 + q] = make_uint4(hu[0], hu[1], hu[2], hu[3]);
            ol[c * 8 + q] = make_uint4(lu[0], lu[1], lu[2], lu[3]);
        }
    }

    if (blockIdx.x < 256) {
        __shared__ int sc[N_RELS];
        for (int i = threadIdx.x; i < N_RELS; i += 256) sc[i] = 0;
        __syncthreads();
        for (int e = blockIdx.x * 256 + threadIdx.x; e < N_EDGES; e += 256 * 256)
            atomicAdd(&sc[et[e]], 1);
        __syncthreads();
        for (int i = threadIdx.x; i < N_RELS; i += 256)
            if (sc[i]) atomicAdd(&d_counts[i], sc[i]);
    }
}

// ---------------- scan + tile table (self-resets d_counts) ----------------
__global__ void scan_tiles_kernel() {
    __shared__ int offs[N_RELS];
    __shared__ int tstart[N_RELS];
    __shared__ int tcnt[N_RELS];
    if (threadIdx.x == 0) {
        int off = 0, ts = 0;
        for (int r = 0; r < N_RELS; r++) {
            int c = d_counts[r];
            offs[r] = off; tstart[r] = ts; tcnt[r] = c;
            d_cursor[r] = off;
            off += c;
            ts += (c + TILE_M - 1) / TILE_M;
        }
        d_num_tiles = ts;
    }
    __syncthreads();
    for (int r = threadIdx.x; r < N_RELS; r += blockDim.x) {
        d_counts[r] = 0;
        int c = tcnt[r], base = offs[r], t0 = tstart[r];
        int nt = (c + TILE_M - 1) / TILE_M;
        for (int t = 0; t < nt; t++) {
            d_tile_rel [t0 + t] = r;
            d_tile_base[t0 + t] = base + t * TILE_M;
            int rem = c - t * TILE_M;
            d_tile_cnt [t0 + t] = rem < TILE_M ? rem : TILE_M;
        }
    }
}

#define SC_EPT 8
__global__ void scatter_kernel(const int* __restrict__ et,
                               const int* __restrict__ src,
                               const int* __restrict__ dst) {
    __shared__ int lcnt[N_RELS];
    __shared__ int lbase[N_RELS];
    int start = blockIdx.x * blockDim.x * SC_EPT;
    for (int i = threadIdx.x; i < N_RELS; i += blockDim.x) lcnt[i] = 0;
    __syncthreads();
    int myrel[SC_EPT];
#pragma unroll
    for (int q = 0; q < SC_EPT; q++) {
        int e = start + threadIdx.x + q * blockDim.x;
        int r = (e < N_EDGES) ? et[e] : -1;
        myrel[q] = r;
        if (r >= 0) atomicAdd(&lcnt[r], 1);
    }
    __syncthreads();
    for (int i = threadIdx.x; i < N_RELS; i += blockDim.x) {
        int c = lcnt[i];
        lbase[i] = c ? atomicAdd(&d_cursor[i], c) : 0;
        lcnt[i] = 0;
    }
    __syncthreads();
#pragma unroll
    for (int q = 0; q < SC_EPT; q++) {
        int e = start + threadIdx.x + q * blockDim.x;
        int r = myrel[q];
        if (r >= 0) {
            int pos = lbase[r] + atomicAdd(&lcnt[r], 1);
            d_psrc[pos] = src[e];
            d_pdst[pos] = dst[e];
        }
    }
}

// ---------------- RGCN layer: 512 threads, 16 warps, coalesced I/O ----------
// Warp grid: 4 edge-blocks(32 rows) x 4 col-quarters(16 cols).
// SMEM: buf0 Xhi [0,16K) Xlo [16K,32K); buf1 [32K,64K);
//       Whi [64K,72K) Wlo [72K,80K); dst[2][128] at [80K,81K)
__global__ void __launch_bounds__(512, 2) rgcn_mma_kernel(int layer)
{
    extern __shared__ __align__(16) uint smem[];
    int nt_total = d_num_tiles;
    int k = (nt_total + P_BLOCKS - 1) / P_BLOCKS;
    int t0 = (int)blockIdx.x * k;
    int t1 = t0 + k; if (t1 > nt_total) t1 = nt_total;
    if (t0 >= t1) return;

    int tid = threadIdx.x;
    uint sbase = smem_u32(smem);
    uint wbB = sbase + 65536u;
    int* s_dstS = (int*)((char*)smem + 81920);   // [2][128]

    int lane = tid & 31, w = tid >> 5;
    int ebh = w & 3;          // edge block (32 rows)
    int cbq = w >> 2;         // col quarter (16 cols)
    int aSel = (lane >> 4) & 1;
    int aRowB = ebh * 32 + (lane & 15);
    int bRow = cbq * 16 + (lane & 7) + ((lane >> 4) & 1) * 8;
    int bSel = (lane >> 3) & 1;
    int g = lane >> 2, tq = lane & 3;

    // coalesced gather map: 8 threads per edge row (2 passes)
    int gm0 = tid >> 3, gc8 = tid & 7;
    // coalesced scatter map: 16 threads per edge row (4 passes)
    int sm0 = tid >> 4, sc16 = tid & 15;

    int cur_rel = -1;

    auto prefetch = [&](int t, int buf) {
        int base = d_tile_base[t];
        int cnt  = d_tile_cnt[t];
        uint xb = sbase + (uint)buf * 32768u;
        int* sd = s_dstS + buf * 128;
#pragma unroll
        for (int p = 0; p < 2; p++) {
            int m = gm0 + p * 64;
            int ei = base + m;
            int eic = ei < (N_EDGES - 1) ? ei : (N_EDGES - 1);
            int srow = d_psrc[eic];
            uint ssz = (m < cnt) ? 16u : 0u;
            const char* ghi = (const char*)(d_hhi_u + (size_t)srow * 32) + gc8 * 16;
            const char* glo = (const char*)(d_hlo_u + (size_t)srow * 32) + gc8 * 16;
            int ph = gc8 ^ (m & 7);
            uint dsthi = xb + (uint)(m * 128 + ph * 16);
            asm volatile("cp.async.ca.shared.global [%0], [%1], 16, %2;"
                         :: "r"(dsthi), "l"(ghi), "r"(ssz) : "memory");
            asm volatile("cp.async.ca.shared.global [%0], [%1], 16, %2;"
                         :: "r"(dsthi + 16384u), "l"(glo), "r"(ssz) : "memory");
            if (gc8 == 0) sd[m] = (m < cnt) ? d_pdst[eic] : -1;
        }
        asm volatile("cp.async.commit_group;" ::: "memory");
    };

    prefetch(t0, 0);

    for (int t = t0; t < t1; t++) {
        int buf = (t - t0) & 1;

        if (t > t0) __syncthreads();              // scatter reads of t-1 done
        bool has_next = (t + 1 < t1);
        if (has_next) prefetch(t + 1, buf ^ 1);

        int rel = d_tile_rel[t];
        if (rel != cur_rel) {
            cur_rel = rel;
            const uint4* WH = (const uint4*)(d_whi_u + ((size_t)layer * N_RELS + rel) * 2048);
            const uint4* WL = (const uint4*)(d_wlo_u + ((size_t)layer * N_RELS + rel) * 2048);
            uint4* wh4 = (uint4*)((char*)smem + 65536);
            uint4* wl4 = (uint4*)((char*)smem + 65536 + 8192);
            int n = tid >> 3, c = tid & 7;
            int ph = c ^ (n & 7);
            wh4[n * 8 + ph] = WH[tid];
            wl4[n * 8 + ph] = WL[tid];
            // visibility covered by the post-wait_group __syncthreads below
        }

        if (has_next) asm volatile("cp.async.wait_group 1;" ::: "memory");
        else          asm volatile("cp.async.wait_group 0;" ::: "memory");
        __syncthreads();                          // X[t] + W + s_dst visible

        uint xbB = sbase + (uint)buf * 32768u;

        float acc[2][2][4];
#pragma unroll
        for (int a = 0; a < 2; a++)
#pragma unroll
            for (int b = 0; b < 2; b++) {
                acc[a][b][0] = acc[a][b][1] = acc[a][b][2] = acc[a][b][3] = 0.f;
            }

#pragma unroll
        for (int ks = 0; ks < 4; ks++) {
            int bChunk = (ks * 2 + bSel) ^ (bRow & 7);
            uint bAddr = wbB + (uint)(bRow * 128 + bChunk * 16);
            uint bh[4], bl[4];
            ldsm_x4(bh, bAddr);
            ldsm_x4(bl, bAddr + 8192u);
#pragma unroll
            for (int mb = 0; mb < 2; mb++) {
                int aRow = aRowB + mb * 16;
                int aChunk = (ks * 2 + aSel) ^ (aRow & 7);
                uint aAddr = xbB + (uint)(aRow * 128 + aChunk * 16);
                uint ah[4], al[4];
                ldsm_x4(ah, aAddr);
                ldsm_x4(al, aAddr + 16384u);
                mma_bf16(acc[mb][0], ah, bh[0], bh[1]);
                mma_bf16(acc[mb][0], ah, bl[0], bl[1]);
                mma_bf16(acc[mb][0], al, bh[0], bh[1]);
                mma_bf16(acc[mb][1], ah, bh[2], bh[3]);
                mma_bf16(acc[mb][1], ah, bl[2], bl[3]);
                mma_bf16(acc[mb][1], al, bh[2], bh[3]);
            }
        }
        __syncthreads();                          // all ldsm of buf done

        // stage into the dead X buffer (XOR layout, 64-float rows)
        float* sOutF = (float*)((char*)smem + (size_t)buf * 32768);
#pragma unroll
        for (int mb = 0; mb < 2; mb++) {
#pragma unroll
            for (int n8 = 0; n8 < 2; n8++) {
                int R = ebh * 32 + mb * 16 + g;
                int C = cbq * 16 + n8 * 8 + 2 * tq;
                int pcA = C ^ ((R & 7) << 3);
                *(float2*)&sOutF[R * 64 + pcA] = make_float2(acc[mb][n8][0], acc[mb][n8][1]);
                int R2 = R + 8;
                int pcB = C ^ ((R2 & 7) << 3);
                *(float2*)&sOutF[R2 * 64 + pcB] = make_float2(acc[mb][n8][2], acc[mb][n8][3]);
            }
        }
        __syncthreads();                          // staging visible

        // coalesced scatter: 16 threads per edge -> whole 256B row per half-warp
        {
            int* sd = s_dstS + buf * 128;
#pragma unroll
            for (int p = 0; p < 4; p++) {
                int m = sm0 + p * 32;
                int dn = sd[m];
                if (dn >= 0) {
                    int pc = (sc16 * 4) ^ ((m & 7) << 3);
                    float4 v = *(const float4*)&sOutF[m * 64 + pc];
                    red_add_v4(d_agg + (size_t)dn * 64 + sc16 * 4, v.x, v.y, v.z, v.w);
                }
            }
        }
    }
}

// ---------------- bias + relu + bf16 split + agg re-zero ----------------
__global__ void bias_relu_kernel(const float* __restrict__ b, int last) {
    int idx = blockIdx.x * blockDim.x + threadIdx.x;
    if (idx >= N_NODES * 32) return;
    int c0 = (idx * 2) & 63;
    float2 a = ((const float2*)d_agg)[idx];
    ((float2*)d_agg)[idx] = make_float2(0.f, 0.f);
    float v0 = fmaxf(a.x + b[c0],     0.0f);
    float v1 = fmaxf(a.y + b[c0 + 1], 0.0f);
    if (last) ((float2*)d_h0)[idx] = make_float2(v0, v1);
    uint hi, lo;
    split2(v0, v1, hi, lo);
    d_hhi_u[idx] = hi;
    d_hlo_u[idx] = lo;
}

// ---------------- graph sum-pool (reads d_h0) ----------------
__global__ void pool_kernel(const int* __restrict__ gid) {
    int idx = blockIdx.x * blockDim.x + threadIdx.x;
    if (idx >= N_NODES * 16) return;
    int n = idx >> 4, c4 = idx & 15;
    float4 v = ((const float4*)(d_h0 + (size_t)n * 64))[c4];
    float* p = d_g + (size_t)gid[n] * 64 + c4 * 4;
    red_add_v4(p, v.x, v.y, v.z, v.w);
}

// ---------------- FC layers ----------------
__global__ void fc64_kernel(int insel, int outsel,
                            const float* __restrict__ W,
                            const float* __restrict__ b) {
    int idx = blockIdx.x * blockDim.x + threadIdx.x;
    if (idx >= N_GRAPHS * 64) return;
    int r = idx >> 6, c = idx & 63;
    const float* x = (insel == 0 ? d_g : d_g2) + r * 64;
    float acc = b[c];
#pragma unroll
    for (int d = 0; d < 64; d++) acc = fmaf(x[d], W[d * 64 + c], acc);
    float v = fmaxf(acc, 0.0f);
    if (outsel == 0) d_g[idx] = v; else d_g2[idx] = v;
}

__global__ void pred_kernel(const float* __restrict__ W,
                            const float* __restrict__ b,
                            float* __restrict__ out) {
    int idx = blockIdx.x * blockDim.x + threadIdx.x;
    if (idx >= N_GRAPHS * 2) return;
    int r = idx >> 1, c = idx & 1;
    const float* x = d_g2 + r * 64;
    float acc = b[c];
#pragma unroll
    for (int d = 0; d < 64; d++) acc = fmaf(x[d], W[d * 2 + c], acc);
    out[idx] = acc;
}

// ---------------- launch ----------------
extern "C" void kernel_launch(void* const* d_in, const int* in_sizes, int n_in,
                              void* d_out, int out_size) {
    const float* node_feats = (const float*)d_in[0];
    const int*   etypes     = (const int*)d_in[1];
    const int*   src        = (const int*)d_in[2];
    const int*   dst        = (const int*)d_in[3];
    const int*   gid        = (const int*)d_in[4];
    const float* Wr[3] = { (const float*)d_in[5], (const float*)d_in[7], (const float*)d_in[9] };
    const float* br[3] = { (const float*)d_in[6], (const float*)d_in[8], (const float*)d_in[10] };
    const float* fcW[3] = { (const float*)d_in[11], (const float*)d_in[13], (const float*)d_in[15] };
    const float* fcb[3] = { (const float*)d_in[12], (const float*)d_in[14], (const float*)d_in[16] };
    const float* predW = (const float*)d_in[17];
    const float* predb = (const float*)d_in[18];

    static int smem_set = 0;
    if (!smem_set) {
        cudaFuncSetAttribute(rgcn_mma_kernel,
                             cudaFuncAttributeMaxDynamicSharedMemorySize, RGCN_SMEM);
        smem_set = 1;
    }

    const int pgrid = (N_NODES * 32 + 255) / 256;

    prep_kernel<<<pgrid, 256>>>(node_feats, etypes, Wr[0], Wr[1], Wr[2]);
    scan_tiles_kernel<<<1, 128>>>();
    scatter_kernel<<<(N_EDGES + 256 * SC_EPT - 1) / (256 * SC_EPT), 256>>>(etypes, src, dst);

    for (int L = 0; L < 3; L++) {
        rgcn_mma_kernel<<<P_BLOCKS, 512, RGCN_SMEM>>>(L);
        bias_relu_kernel<<<pgrid, 256>>>(br[L], L == 2 ? 1 : 0);
    }

    pool_kernel<<<(N_NODES * 16 + 255) / 256, 256>>>(gid);

    const int fgrid = (N_GRAPHS * 64 + 255) / 256;
    fc64_kernel<<<fgrid, 256>>>(0, 1, fcW[0], fcb[0]);
    fc64_kernel<<<fgrid, 256>>>(1, 0, fcW[1], fcb[1]);
    fc64_kernel<<<fgrid, 256>>>(0, 1, fcW[2], fcb[2]);
    pred_kernel<<<(N_GRAPHS * 2 + 255) / 256, 256>>>(predW, predb, (float*)d_out);
}

// round 10
// speedup vs baseline: 1.8292x; 1.1019x over previous
#include <cuda_runtime.h>
#include <cuda_fp16.h>
#include <cstdint>

typedef unsigned int uint;

#define N_NODES 50000
#define N_EDGES 800000
#define N_RELS  65
#define D       64
#define N_GRAPHS 512

#define TILE_M 128
#define MAX_TILES (N_EDGES / TILE_M + N_RELS)   // 6315
#define P_BLOCKS 296
#define RGCN_SMEM 82944  // X 2x16K | W 2x8K | out 32K | dst 1K

// ---------------- scratch (device globals; no allocation) ----------------
__device__ float d_h0 [N_NODES * D];
__device__ float d_agg[N_NODES * D];
__device__ float d_g [N_GRAPHS * D];
__device__ float d_g2[N_GRAPHS * D];

__device__ uint d_hf_u[N_NODES * 32];           // fp16 X plane, 2 per uint
__device__ uint d_w1_u[3 * N_RELS * 2048];      // W^T fp16 main plane
__device__ uint d_w2_u[3 * N_RELS * 2048];      // W^T fp16 residual plane

__device__ int d_counts[N_RELS];                // zero-init; self-resetting
__device__ int d_cursor[N_RELS];
__device__ int d_psrc[N_EDGES];
__device__ int d_pdst[N_EDGES];
__device__ int d_tile_rel [MAX_TILES];
__device__ int d_tile_base[MAX_TILES];
__device__ int d_tile_cnt [MAX_TILES];
__device__ int d_num_tiles;

// ---------------- helpers ----------------
__device__ __forceinline__ void red_add_v4(float* p, float a, float b, float c, float d) {
    asm volatile("red.global.add.v4.f32 [%0], {%1, %2, %3, %4};"
                 :: "l"(p), "f"(a), "f"(b), "f"(c), "f"(d) : "memory");
}

__device__ __forceinline__ void mma_f16(float acc[4], const uint a[4], uint b0, uint b1) {
    asm volatile("mma.sync.aligned.m16n8k16.row.col.f32.f16.f16.f32 "
                 "{%0,%1,%2,%3}, {%4,%5,%6,%7}, {%8,%9}, {%0,%1,%2,%3};"
                 : "+f"(acc[0]), "+f"(acc[1]), "+f"(acc[2]), "+f"(acc[3])
                 : "r"(a[0]), "r"(a[1]), "r"(a[2]), "r"(a[3]), "r"(b0), "r"(b1));
}

__device__ __forceinline__ void ldsm_x4(uint r[4], uint32_t addr) {
    asm volatile("ldmatrix.sync.aligned.m8n8.x4.shared.b16 {%0,%1,%2,%3}, [%4];"
                 : "=r"(r[0]), "=r"(r[1]), "=r"(r[2]), "=r"(r[3]) : "r"(addr));
}

__device__ __forceinline__ uint32_t smem_u32(const void* p) {
    uint32_t a;
    asm("{ .reg .u64 t; cvta.to.shared.u64 t, %1; cvt.u32.u64 %0, t; }" : "=r"(a) : "l"(p));
    return a;
}

__device__ __forceinline__ unsigned short h_bits(__half h) {
    return *reinterpret_cast<unsigned short*>(&h);
}
__device__ __forceinline__ uint pack_f16x2(float a, float b) {
    __half h0 = __float2half_rn(a);
    __half h1 = __float2half_rn(b);
    return (uint)h_bits(h0) | ((uint)h_bits(h1) << 16);
}
// W split: w = w1 + w2 (both fp16)
__device__ __forceinline__ void splitw(float v0, float v1, uint& p1, uint& p2) {
    __half a0 = __float2half_rn(v0);
    __half a1 = __float2half_rn(v1);
    float r0 = v0 - __half2float(a0);
    float r1 = v1 - __half2float(a1);
    __half b0 = __float2half_rn(r0);
    __half b1 = __float2half_rn(r1);
    p1 = (uint)h_bits(a0) | ((uint)h_bits(a1) << 16);
    p2 = (uint)h_bits(b0) | ((uint)h_bits(b1) << 16);
}

// ---------------- prep: conv_x + zero agg/g + conv_w + hist (fused) ---------
__global__ void prep_kernel(const float* __restrict__ nf,
                            const int* __restrict__ et,
                            const float* __restrict__ W1,
                            const float* __restrict__ W2,
                            const float* __restrict__ W3) {
    int idx = blockIdx.x * 256 + threadIdx.x;

    if (idx < N_NODES * 32) {
        float2 v = ((const float2*)nf)[idx];
        d_hf_u[idx] = pack_f16x2(v.x, v.y);
        ((float2*)d_agg)[idx] = make_float2(0.f, 0.f);
    }
    if (idx < N_GRAPHS * 32) ((float2*)d_g)[idx] = make_float2(0.f, 0.f);

    if (idx < 3 * N_RELS * 64) {
        int l = idx / (N_RELS * 64), rc = idx % (N_RELS * 64);
        int r = rc >> 6, c = rc & 63;
        const float* W = (l == 0 ? W1 : (l == 1 ? W2 : W3)) + (size_t)r * 4096 + c;
        uint4* o1 = (uint4*)(d_w1_u + ((size_t)l * N_RELS + r) * 2048);
        uint4* o2 = (uint4*)(d_w2_u + ((size_t)l * N_RELS + r) * 2048);
#pragma unroll
        for (int q = 0; q < 8; q++) {
            uint u1[4], u2[4];
#pragma unroll
            for (int p = 0; p < 4; p++) {
                float v0 = W[(q * 8 + p * 2 + 0) * 64];
                float v1 = W[(q * 8 + p * 2 + 1) * 64];
                splitw(v0, v1, u1[p], u2[p]);
            }
            o1[c * 8 + q] = make_uint4(u1[0], u1[1], u1[2], u1[3]);
            o2[c * 8 + q] = make_uint4(u2[0], u2[1], u2[2], u2[3]);
        }
    }

    if (blockIdx.x < 256) {
        __shared__ int sc[N_RELS];
        for (int i = threadIdx.x; i < N_RELS; i += 256) sc[i] = 0;
        __syncthreads();
        for (int e = blockIdx.x * 256 + threadIdx.x; e < N_EDGES; e += 256 * 256)
            atomicAdd(&sc[et[e]], 1);
        __syncthreads();
        for (int i = threadIdx.x; i < N_RELS; i += 256)
            if (sc[i]) atomicAdd(&d_counts[i], sc[i]);
    }
}

// ---------------- scan + tile table (self-resets d_counts) ----------------
__global__ void scan_tiles_kernel() {
    __shared__ int offs[N_RELS];
    __shared__ int tstart[N_RELS];
    __shared__ int tcnt[N_RELS];
    if (threadIdx.x == 0) {
        int off = 0, ts = 0;
        for (int r = 0; r < N_RELS; r++) {
            int c = d_counts[r];
            offs[r] = off; tstart[r] = ts; tcnt[r] = c;
            d_cursor[r] = off;
            off += c;
            ts += (c + TILE_M - 1) / TILE_M;
        }
        d_num_tiles = ts;
    }
    __syncthreads();
    for (int r = threadIdx.x; r < N_RELS; r += blockDim.x) {
        d_counts[r] = 0;
        int c = tcnt[r], base = offs[r], t0 = tstart[r];
        int nt = (c + TILE_M - 1) / TILE_M;
        for (int t = 0; t < nt; t++) {
            d_tile_rel [t0 + t] = r;
            d_tile_base[t0 + t] = base + t * TILE_M;
            int rem = c - t * TILE_M;
            d_tile_cnt [t0 + t] = rem < TILE_M ? rem : TILE_M;
        }
    }
}

#define SC_EPT 8
__global__ void scatter_kernel(const int* __restrict__ et,
                               const int* __restrict__ src,
                               const int* __restrict__ dst) {
    __shared__ int lcnt[N_RELS];
    __shared__ int lbase[N_RELS];
    int start = blockIdx.x * blockDim.x * SC_EPT;
    for (int i = threadIdx.x; i < N_RELS; i += blockDim.x) lcnt[i] = 0;
    __syncthreads();
    int myrel[SC_EPT];
#pragma unroll
    for (int q = 0; q < SC_EPT; q++) {
        int e = start + threadIdx.x + q * blockDim.x;
        int r = (e < N_EDGES) ? et[e] : -1;
        myrel[q] = r;
        if (r >= 0) atomicAdd(&lcnt[r], 1);
    }
    __syncthreads();
    for (int i = threadIdx.x; i < N_RELS; i += blockDim.x) {
        int c = lcnt[i];
        lbase[i] = c ? atomicAdd(&d_cursor[i], c) : 0;
        lcnt[i] = 0;
    }
    __syncthreads();
#pragma unroll
    for (int q = 0; q < SC_EPT; q++) {
        int e = start + threadIdx.x + q * blockDim.x;
        int r = myrel[q];
        if (r >= 0) {
            int pos = lbase[r] + atomicAdd(&lcnt[r], 1);
            d_psrc[pos] = src[e];
            d_pdst[pos] = dst[e];
        }
    }
}

// ---------------- RGCN layer: fp16 2-term, 512 threads, coalesced I/O -------
// Warp grid: 4 edge-blocks(32 rows) x 4 col-quarters(16 cols).
// SMEM: X buf0 [0,16K) buf1 [16K,32K); W1 [32K,40K) W2 [40K,48K);
//       out [48K,80K); dst[2][128] at [80K,81K)
__global__ void __launch_bounds__(512, 2) rgcn_mma_kernel(int layer)
{
    extern __shared__ __align__(16) uint smem[];
    int nt_total = d_num_tiles;
    int k = (nt_total + P_BLOCKS - 1) / P_BLOCKS;
    int t0 = (int)blockIdx.x * k;
    int t1 = t0 + k; if (t1 > nt_total) t1 = nt_total;
    if (t0 >= t1) return;

    int tid = threadIdx.x;
    uint sbase = smem_u32(smem);
    uint wb1 = sbase + 32768u;
    int* s_dstS = (int*)((char*)smem + 81920);   // [2][128]
    float* sOutF = (float*)((char*)smem + 49152);

    int lane = tid & 31, w = tid >> 5;
    int ebh = w & 3;          // edge block (32 rows)
    int cbq = w >> 2;         // col quarter (16 cols)
    int aSel = (lane >> 4) & 1;
    int aRowB = ebh * 32 + (lane & 15);
    int bRow = cbq * 16 + (lane & 7) + ((lane >> 4) & 1) * 8;
    int bSel = (lane >> 3) & 1;
    int g = lane >> 2, tq = lane & 3;

    // coalesced gather map: 8 threads per edge row (2 passes)
    int gm0 = tid >> 3, gc8 = tid & 7;
    // coalesced scatter map: 16 threads per edge row (4 passes)
    int sm0 = tid >> 4, sc16 = tid & 15;

    int cur_rel = -1;

    auto prefetch = [&](int t, int buf) {
        int base = d_tile_base[t];
        int cnt  = d_tile_cnt[t];
        uint xb = sbase + (uint)buf * 16384u;
        int* sd = s_dstS + buf * 128;
#pragma unroll
        for (int p = 0; p < 2; p++) {
            int m = gm0 + p * 64;
            int ei = base + m;
            int eic = ei < (N_EDGES - 1) ? ei : (N_EDGES - 1);
            int srow = d_psrc[eic];
            uint ssz = (m < cnt) ? 16u : 0u;
            const char* gsrc = (const char*)(d_hf_u + (size_t)srow * 32) + gc8 * 16;
            int ph = gc8 ^ (m & 7);
            uint dsts = xb + (uint)(m * 128 + ph * 16);
            asm volatile("cp.async.ca.shared.global [%0], [%1], 16, %2;"
                         :: "r"(dsts), "l"(gsrc), "r"(ssz) : "memory");
            if (gc8 == 0) sd[m] = (m < cnt) ? d_pdst[eic] : -1;
        }
        asm volatile("cp.async.commit_group;" ::: "memory");
    };

    prefetch(t0, 0);

    for (int t = t0; t < t1; t++) {
        int buf = (t - t0) & 1;

        if (t > t0) __syncthreads();              // scatter reads of t-1 done
        bool has_next = (t + 1 < t1);
        if (has_next) prefetch(t + 1, buf ^ 1);

        int rel = d_tile_rel[t];
        if (rel != cur_rel) {
            cur_rel = rel;
            const uint4* W1g = (const uint4*)(d_w1_u + ((size_t)layer * N_RELS + rel) * 2048);
            const uint4* W2g = (const uint4*)(d_w2_u + ((size_t)layer * N_RELS + rel) * 2048);
            uint4* w14 = (uint4*)((char*)smem + 32768);
            uint4* w24 = (uint4*)((char*)smem + 40960);
            int n = tid >> 3, c = tid & 7;
            int ph = c ^ (n & 7);
            w14[n * 8 + ph] = W1g[tid];
            w24[n * 8 + ph] = W2g[tid];
            // visibility covered by the post-wait_group __syncthreads below
        }

        if (has_next) asm volatile("cp.async.wait_group 1;" ::: "memory");
        else          asm volatile("cp.async.wait_group 0;" ::: "memory");
        __syncthreads();                          // X[t] + W + s_dst visible

        uint xbB = sbase + (uint)buf * 16384u;

        float acc[2][2][4];
#pragma unroll
        for (int a = 0; a < 2; a++)
#pragma unroll
            for (int b = 0; b < 2; b++) {
                acc[a][b][0] = acc[a][b][1] = acc[a][b][2] = acc[a][b][3] = 0.f;
            }

#pragma unroll
        for (int ks = 0; ks < 4; ks++) {
            int bChunk = (ks * 2 + bSel) ^ (bRow & 7);
            uint bAddr = wb1 + (uint)(bRow * 128 + bChunk * 16);
            uint bh[4], bl[4];
            ldsm_x4(bh, bAddr);
            ldsm_x4(bl, bAddr + 8192u);           // W2 plane
#pragma unroll
            for (int mb = 0; mb < 2; mb++) {
                int aRow = aRowB + mb * 16;
                int aChunk = (ks * 2 + aSel) ^ (aRow & 7);
                uint aAddr = xbB + (uint)(aRow * 128 + aChunk * 16);
                uint ah[4];
                ldsm_x4(ah, aAddr);
                mma_f16(acc[mb][0], ah, bh[0], bh[1]);
                mma_f16(acc[mb][0], ah, bl[0], bl[1]);
                mma_f16(acc[mb][1], ah, bh[2], bh[3]);
                mma_f16(acc[mb][1], ah, bl[2], bl[3]);
            }
        }
        __syncthreads();                          // all ldsm of buf done

        // stage into dedicated out region (XOR layout, 64-float rows)
#pragma unroll
        for (int mb = 0; mb < 2; mb++) {
#pragma unroll
            for (int n8 = 0; n8 < 2; n8++) {
                int R = ebh * 32 + mb * 16 + g;
                int C = cbq * 16 + n8 * 8 + 2 * tq;
                int pcA = C ^ ((R & 7) << 3);
                *(float2*)&sOutF[R * 64 + pcA] = make_float2(acc[mb][n8][0], acc[mb][n8][1]);
                int R2 = R + 8;
                int pcB = C ^ ((R2 & 7) << 3);
                *(float2*)&sOutF[R2 * 64 + pcB] = make_float2(acc[mb][n8][2], acc[mb][n8][3]);
            }
        }
        __syncthreads();                          // staging visible

        // coalesced scatter: 16 threads per edge -> whole 256B row per half-warp
        {
            int* sd = s_dstS + buf * 128;
#pragma unroll
            for (int p = 0; p < 4; p++) {
                int m = sm0 + p * 32;
                int dn = sd[m];
                if (dn >= 0) {
                    int pc = (sc16 * 4) ^ ((m & 7) << 3);
                    float4 v = *(const float4*)&sOutF[m * 64 + pc];
                    red_add_v4(d_agg + (size_t)dn * 64 + sc16 * 4, v.x, v.y, v.z, v.w);
                }
            }
        }
    }
}

// ---------------- bias + relu + fp16 convert + agg re-zero ----------------
__global__ void bias_relu_kernel(const float* __restrict__ b, int last) {
    int idx = blockIdx.x * blockDim.x + threadIdx.x;
    if (idx >= N_NODES * 32) return;
    int c0 = (idx * 2) & 63;
    float2 a = ((const float2*)d_agg)[idx];
    ((float2*)d_agg)[idx] = make_float2(0.f, 0.f);
    float v0 = fmaxf(a.x + b[c0],     0.0f);
    float v1 = fmaxf(a.y + b[c0 + 1], 0.0f);
    if (last) ((float2*)d_h0)[idx] = make_float2(v0, v1);
    d_hf_u[idx] = pack_f16x2(v0, v1);
}

// ---------------- graph sum-pool (reads d_h0) ----------------
__global__ void pool_kernel(const int* __restrict__ gid) {
    int idx = blockIdx.x * blockDim.x + threadIdx.x;
    if (idx >= N_NODES * 16) return;
    int n = idx >> 4, c4 = idx & 15;
    float4 v = ((const float4*)(d_h0 + (size_t)n * 64))[c4];
    float* p = d_g + (size_t)gid[n] * 64 + c4 * 4;
    red_add_v4(p, v.x, v.y, v.z, v.w);
}

// ---------------- FC layers ----------------
__global__ void fc64_kernel(int insel, int outsel,
                            const float* __restrict__ W,
                            const float* __restrict__ b) {
    int idx = blockIdx.x * blockDim.x + threadIdx.x;
    if (idx >= N_GRAPHS * 64) return;
    int r = idx >> 6, c = idx & 63;
    const float* x = (insel == 0 ? d_g : d_g2) + r * 64;
    float acc = b[c];
#pragma unroll
    for (int d = 0; d < 64; d++) acc = fmaf(x[d], W[d * 64 + c], acc);
    float v = fmaxf(acc, 0.0f);
    if (outsel == 0) d_g[idx] = v; else d_g2[idx] = v;
}

__global__ void pred_kernel(const float* __restrict__ W,
                            const float* __restrict__ b,
                            float* __restrict__ out) {
    int idx = blockIdx.x * blockDim.x + threadIdx.x;
    if (idx >= N_GRAPHS * 2) return;
    int r = idx >> 1, c = idx & 1;
    const float* x = d_g2 + r * 64;
    float acc = b[c];
#pragma unroll
    for (int d = 0; d < 64; d++) acc = fmaf(x[d], W[d * 2 + c], acc);
    out[idx] = acc;
}

// ---------------- launch ----------------
extern "C" void kernel_launch(void* const* d_in, const int* in_sizes, int n_in,
                              void* d_out, int out_size) {
    const float* node_feats = (const float*)d_in[0];
    const int*   etypes     = (const int*)d_in[1];
    const int*   src        = (const int*)d_in[2];
    const int*   dst        = (const int*)d_in[3];
    const int*   gid        = (const int*)d_in[4];
    const float* Wr[3] = { (const float*)d_in[5], (const float*)d_in[7], (const float*)d_in[9] };
    const float* br[3] = { (const float*)d_in[6], (const float*)d_in[8], (const float*)d_in[10] };
    const float* fcW[3] = { (const float*)d_in[11], (const float*)d_in[13], (const float*)d_in[15] };
    const float* fcb[3] = { (const float*)d_in[12], (const float*)d_in[14], (const float*)d_in[16] };
    const float* predW = (const float*)d_in[17];
    const float* predb = (const float*)d_in[18];

    static int smem_set = 0;
    if (!smem_set) {
        cudaFuncSetAttribute(rgcn_mma_kernel,
                             cudaFuncAttributeMaxDynamicSharedMemorySize, RGCN_SMEM);
        smem_set = 1;
    }

    const int pgrid = (N_NODES * 32 + 255) / 256;

    prep_kernel<<<pgrid, 256>>>(node_feats, etypes, Wr[0], Wr[1], Wr[2]);
    scan_tiles_kernel<<<1, 128>>>();
    scatter_kernel<<<(N_EDGES + 256 * SC_EPT - 1) / (256 * SC_EPT), 256>>>(etypes, src, dst);

    for (int L = 0; L < 3; L++) {
        rgcn_mma_kernel<<<P_BLOCKS, 512, RGCN_SMEM>>>(L);
        bias_relu_kernel<<<pgrid, 256>>>(br[L], L == 2 ? 1 : 0);
    }

    pool_kernel<<<(N_NODES * 16 + 255) / 256, 256>>>(gid);

    const int fgrid = (N_GRAPHS * 64 + 255) / 256;
    fc64_kernel<<<fgrid, 256>>>(0, 1, fcW[0], fcb[0]);
    fc64_kernel<<<fgrid, 256>>>(1, 0, fcW[1], fcb[1]);
    fc64_kernel<<<fgrid, 256>>>(0, 1, fcW[2], fcb[2]);
    pred_kernel<<<(N_GRAPHS * 2 + 255) / 256, 256>>>(predW, predb, (float*)d_out);
}